// round 1
// baseline (speedup 1.0000x reference)
#include <cuda_runtime.h>
#include <cuda_bf16.h>
#include <math.h>

#define B_  2
#define S_  2048
#define D_  1024
#define H_  16
#define DK  64
#define BH_ (B_*H_)

// ---------------- scratch (static device allocations; no cudaMalloc) ----------------
__device__ float g_q[(size_t)B_*S_*D_];
__device__ float g_k[(size_t)B_*S_*D_];
__device__ float g_v[(size_t)B_*S_*D_];
__device__ float g_attn[(size_t)B_*S_*D_];
__device__ float g_scores[(size_t)BH_*S_*S_];   // 512 MB
__device__ float g_m[BH_*S_];
__device__ float g_z[BH_*S_];

// ---------------- generic 128x128 fp32 GEMM: C[M,1024] = A[M,1024] @ W[1024,1024] ----
__global__ __launch_bounds__(256, 2) void gemm128(const float* __restrict__ A,
                                                  const float* __restrict__ W,
                                                  float* __restrict__ C) {
    __shared__ float As[16*128];   // [kk][m]
    __shared__ float Bs[16*128];   // [kk][n]
    const int tid = threadIdx.x;
    const int ty = tid >> 4, tx = tid & 15;
    const int m0 = blockIdx.y * 128, n0 = blockIdx.x * 128;

    float acc[8][8];
#pragma unroll
    for (int i = 0; i < 8; i++)
#pragma unroll
        for (int j = 0; j < 8; j++) acc[i][j] = 0.f;

    for (int k0 = 0; k0 < 1024; k0 += 16) {
        // A tile 128x16 -> As[kk][m] (transposed store)
#pragma unroll
        for (int u = 0; u < 2; u++) {
            int idx = tid * 2 + u;         // 0..511
            int m = idx >> 2, c4 = idx & 3;
            float4 v = *(const float4*)&A[(size_t)(m0 + m) * 1024 + k0 + c4 * 4];
            As[(c4 * 4 + 0) * 128 + m] = v.x;
            As[(c4 * 4 + 1) * 128 + m] = v.y;
            As[(c4 * 4 + 2) * 128 + m] = v.z;
            As[(c4 * 4 + 3) * 128 + m] = v.w;
        }
        // B tile 16x128 -> Bs[kk][n] (direct)
#pragma unroll
        for (int u = 0; u < 2; u++) {
            int idx = tid * 2 + u;
            int kk = idx >> 5, n4 = idx & 31;
            *(float4*)&Bs[kk * 128 + n4 * 4] =
                *(const float4*)&W[(size_t)(k0 + kk) * 1024 + n0 + n4 * 4];
        }
        __syncthreads();
#pragma unroll
        for (int kk = 0; kk < 16; kk++) {
            float4 a0 = *(const float4*)&As[kk * 128 + ty * 8];
            float4 a1 = *(const float4*)&As[kk * 128 + ty * 8 + 4];
            float4 b0 = *(const float4*)&Bs[kk * 128 + tx * 8];
            float4 b1 = *(const float4*)&Bs[kk * 128 + tx * 8 + 4];
            float a[8] = {a0.x, a0.y, a0.z, a0.w, a1.x, a1.y, a1.z, a1.w};
            float b[8] = {b0.x, b0.y, b0.z, b0.w, b1.x, b1.y, b1.z, b1.w};
#pragma unroll
            for (int i = 0; i < 8; i++)
#pragma unroll
                for (int j = 0; j < 8; j++) acc[i][j] = fmaf(a[i], b[j], acc[i][j]);
        }
        __syncthreads();
    }
#pragma unroll
    for (int i = 0; i < 8; i++) {
        size_t off = (size_t)(m0 + ty * 8 + i) * 1024 + n0 + tx * 8;
        *(float4*)&C[off]     = make_float4(acc[i][0], acc[i][1], acc[i][2], acc[i][3]);
        *(float4*)&C[off + 4] = make_float4(acc[i][4], acc[i][5], acc[i][6], acc[i][7]);
    }
}

// ---------------- RoPE (in-place on q and k) ----------------
__global__ void rope_kernel(float* __restrict__ q, float* __restrict__ k,
                            const float* __restrict__ fc, const float* __restrict__ fs) {
    int idx = blockIdx.x * blockDim.x + threadIdx.x;   // B*S*H*32 = 2097152
    int i = idx & 31;
    int h = (idx >> 5) & 15;
    int s = (idx >> 9) & (S_ - 1);
    int b = idx >> 20;
    float c  = fc[s * 32 + i];
    float sn = fs[s * 32 + i];
    size_t base = ((size_t)(b * S_ + s)) * D_ + h * DK + 2 * i;
    float a0 = q[base], a1 = q[base + 1];
    q[base]     = a0 * c - a1 * sn;
    q[base + 1] = a0 * sn + a1 * c;
    a0 = k[base]; a1 = k[base + 1];
    k[base]     = a0 * c - a1 * sn;
    k[base + 1] = a0 * sn + a1 * c;
}

// ---------------- pass 1: scores = QK^T/8 -> scratch, online (m, Z) ----------------
__global__ __launch_bounds__(256, 2) void attn_pass1(const float* __restrict__ q,
                                                     const float* __restrict__ k) {
    extern __shared__ float sm[];
    float* Qs = sm;             // [64][128]  (d-major, transposed)
    float* Ks = sm + 64 * 128;  // [64][128]
    const int tid = threadIdx.x;
    const int ty = tid >> 4, tx = tid & 15;
    const int bh = blockIdx.y, b = bh >> 4, h = bh & 15;
    const int q0 = blockIdx.x * 128;

    // load Q tile transposed
    {
        const float* src = q + ((size_t)(b * S_) + q0) * D_ + h * DK;
#pragma unroll
        for (int u = 0; u < 8; u++) {
            int idx = tid * 8 + u;          // 0..2047 float4s
            int row = idx >> 4, c4 = idx & 15;
            float4 v = *(const float4*)&src[(size_t)row * D_ + c4 * 4];
            Qs[(c4 * 4 + 0) * 128 + row] = v.x;
            Qs[(c4 * 4 + 1) * 128 + row] = v.y;
            Qs[(c4 * 4 + 2) * 128 + row] = v.z;
            Qs[(c4 * 4 + 3) * 128 + row] = v.w;
        }
    }

    float mrow[8], zrow[8];
#pragma unroll
    for (int i = 0; i < 8; i++) { mrow[i] = -1e30f; zrow[i] = 0.f; }

    for (int kt = 0; kt < 16; kt++) {
        const int k0 = kt * 128;
        __syncthreads();   // previous tile's readers done (also fences Q stores on iter 0)
        {
            const float* src = k + ((size_t)(b * S_) + k0) * D_ + h * DK;
#pragma unroll
            for (int u = 0; u < 8; u++) {
                int idx = tid * 8 + u;
                int row = idx >> 4, c4 = idx & 15;
                float4 v = *(const float4*)&src[(size_t)row * D_ + c4 * 4];
                Ks[(c4 * 4 + 0) * 128 + row] = v.x;
                Ks[(c4 * 4 + 1) * 128 + row] = v.y;
                Ks[(c4 * 4 + 2) * 128 + row] = v.z;
                Ks[(c4 * 4 + 3) * 128 + row] = v.w;
            }
        }
        __syncthreads();

        float acc[8][8];
#pragma unroll
        for (int i = 0; i < 8; i++)
#pragma unroll
            for (int j = 0; j < 8; j++) acc[i][j] = 0.f;

#pragma unroll 4
        for (int d = 0; d < 64; d++) {
            float4 a0 = *(const float4*)&Qs[d * 128 + ty * 8];
            float4 a1 = *(const float4*)&Qs[d * 128 + ty * 8 + 4];
            float4 b0 = *(const float4*)&Ks[d * 128 + tx * 8];
            float4 b1 = *(const float4*)&Ks[d * 128 + tx * 8 + 4];
            float a[8] = {a0.x, a0.y, a0.z, a0.w, a1.x, a1.y, a1.z, a1.w};
            float bb[8] = {b0.x, b0.y, b0.z, b0.w, b1.x, b1.y, b1.z, b1.w};
#pragma unroll
            for (int i = 0; i < 8; i++)
#pragma unroll
                for (int j = 0; j < 8; j++) acc[i][j] = fmaf(a[i], bb[j], acc[i][j]);
        }

#pragma unroll
        for (int i = 0; i < 8; i++) {
#pragma unroll
            for (int j = 0; j < 8; j++) acc[i][j] *= 0.125f;
            size_t off = ((size_t)bh * S_ + q0 + ty * 8 + i) * S_ + k0 + tx * 8;
            *(float4*)&g_scores[off]     = make_float4(acc[i][0], acc[i][1], acc[i][2], acc[i][3]);
            *(float4*)&g_scores[off + 4] = make_float4(acc[i][4], acc[i][5], acc[i][6], acc[i][7]);

            float lm = acc[i][0];
#pragma unroll
            for (int j = 1; j < 8; j++) lm = fmaxf(lm, acc[i][j]);
#pragma unroll
            for (int o = 8; o; o >>= 1) lm = fmaxf(lm, __shfl_xor_sync(0xffffffffu, lm, o));
            float mn = fmaxf(mrow[i], lm);
            float ls = 0.f;
#pragma unroll
            for (int j = 0; j < 8; j++) ls += __expf(acc[i][j] - mn);
#pragma unroll
            for (int o = 8; o; o >>= 1) ls += __shfl_xor_sync(0xffffffffu, ls, o);
            zrow[i] = zrow[i] * __expf(mrow[i] - mn) + ls;
            mrow[i] = mn;
        }
    }

    if (tx == 0) {
#pragma unroll
        for (int i = 0; i < 8; i++) {
            int qg = q0 + ty * 8 + i;
            g_m[bh * S_ + qg] = mrow[i];
            g_z[bh * S_ + qg] = zrow[i];
        }
    }
}

// ---------------- pass 2: t = exp(softmax(s)), out = (t @ V) / sum(t) ----------------
__global__ __launch_bounds__(256, 2) void attn_pass2(const float* __restrict__ v,
                                                     float* __restrict__ attn) {
    extern __shared__ float sm[];
    float* Ts = sm;             // [64 k][128 q] floats, XOR-swizzled float4 slots
    float* Vs = sm + 64 * 128;  // [64 k][64 dv]
    float4* Ts4 = (float4*)Ts;
    const int tid = threadIdx.x;
    const int ty = tid >> 4, tx = tid & 15;
    const int bh = blockIdx.y, b = bh >> 4, h = bh & 15;
    const int q0 = blockIdx.x * 128;

    float mq[8], iz[8];
#pragma unroll
    for (int i = 0; i < 8; i++) {
        int qg = q0 + ty * 8 + i;
        mq[i] = g_m[bh * S_ + qg];
        iz[i] = 1.0f / g_z[bh * S_ + qg];
    }

    float acc[8][4];
    float tsum[8];
#pragma unroll
    for (int i = 0; i < 8; i++) {
        tsum[i] = 0.f;
#pragma unroll
        for (int j = 0; j < 4; j++) acc[i][j] = 0.f;
    }

    for (int kt = 0; kt < 32; kt++) {
        const int k0 = kt * 64;
        __syncthreads();   // previous tile readers done
        // V tile 64x64
        {
            const float* src = v + ((size_t)(b * S_) + k0) * D_ + h * DK;
#pragma unroll
            for (int u = 0; u < 4; u++) {
                int idx = tid * 4 + u;          // 0..1023 float4s
                int row = idx >> 4, c4 = idx & 15;
                *(float4*)&Vs[row * 64 + c4 * 4] =
                    *(const float4*)&src[(size_t)row * D_ + c4 * 4];
            }
        }
        // t = exp(exp(s - m)/Z)
        float tv[8][4];
#pragma unroll
        for (int i = 0; i < 8; i++) {
            size_t off = ((size_t)bh * S_ + q0 + ty * 8 + i) * S_ + k0 + tx * 4;
            float4 s4 = *(const float4*)&g_scores[off];
            tv[i][0] = __expf(__expf(s4.x - mq[i]) * iz[i]);
            tv[i][1] = __expf(__expf(s4.y - mq[i]) * iz[i]);
            tv[i][2] = __expf(__expf(s4.z - mq[i]) * iz[i]);
            tv[i][3] = __expf(__expf(s4.w - mq[i]) * iz[i]);
            tsum[i] += tv[i][0] + tv[i][1] + tv[i][2] + tv[i][3];
        }
        // store t transposed into Ts[k][q] with swizzle slot = q4 ^ (k>>2)
#pragma unroll
        for (int p = 0; p < 2; p++)
#pragma unroll
            for (int j = 0; j < 4; j++) {
                int kk = tx * 4 + j;
                int slot = (ty * 2 + p) ^ tx;    // tx == kk>>2
                Ts4[kk * 32 + slot] =
                    make_float4(tv[p * 4 + 0][j], tv[p * 4 + 1][j],
                                tv[p * 4 + 2][j], tv[p * 4 + 3][j]);
            }
        __syncthreads();

#pragma unroll 4
        for (int kk = 0; kk < 64; kk++) {
            float4 t0 = Ts4[kk * 32 + ((ty * 2) ^ (kk >> 2))];
            float4 t1 = Ts4[kk * 32 + ((ty * 2 + 1) ^ (kk >> 2))];
            float4 v4 = *(const float4*)&Vs[kk * 64 + tx * 4];
            float tq[8] = {t0.x, t0.y, t0.z, t0.w, t1.x, t1.y, t1.z, t1.w};
            float vv[4] = {v4.x, v4.y, v4.z, v4.w};
#pragma unroll
            for (int i = 0; i < 8; i++)
#pragma unroll
                for (int j = 0; j < 4; j++) acc[i][j] = fmaf(tq[i], vv[j], acc[i][j]);
        }
    }

#pragma unroll
    for (int i = 0; i < 8; i++)
#pragma unroll
        for (int o = 8; o; o >>= 1) tsum[i] += __shfl_xor_sync(0xffffffffu, tsum[i], o);

#pragma unroll
    for (int i = 0; i < 8; i++) {
        float r = 1.0f / tsum[i];
        size_t off = ((size_t)(b * S_) + q0 + ty * 8 + i) * D_ + h * DK + tx * 4;
        *(float4*)&attn[off] =
            make_float4(acc[i][0] * r, acc[i][1] * r, acc[i][2] * r, acc[i][3] * r);
    }
}

// ---------------- launch ----------------
extern "C" void kernel_launch(void* const* d_in, const int* in_sizes, int n_in,
                              void* d_out, int out_size) {
    const float* x  = (const float*)d_in[0];
    const float* fc = (const float*)d_in[1];
    const float* fs = (const float*)d_in[2];
    const float* Wq = (const float*)d_in[3];
    const float* Wk = (const float*)d_in[4];
    const float* Wv = (const float*)d_in[5];
    const float* Wo = (const float*)d_in[6];
    float* out = (float*)d_out;

    float *q, *k, *v, *attn;
    cudaGetSymbolAddress((void**)&q, g_q);
    cudaGetSymbolAddress((void**)&k, g_k);
    cudaGetSymbolAddress((void**)&v, g_v);
    cudaGetSymbolAddress((void**)&attn, g_attn);

    cudaFuncSetAttribute(attn_pass1, cudaFuncAttributeMaxDynamicSharedMemorySize, 65536);
    cudaFuncSetAttribute(attn_pass2, cudaFuncAttributeMaxDynamicSharedMemorySize, 49152);

    dim3 ggrid(8, 32);                         // 1024/128 x 4096/128
    gemm128<<<ggrid, 256>>>(x, Wq, q);
    gemm128<<<ggrid, 256>>>(x, Wk, k);
    gemm128<<<ggrid, 256>>>(x, Wv, v);

    rope_kernel<<<(B_*S_*H_*(DK/2)) / 256, 256>>>(q, k, fc, fs);

    attn_pass1<<<dim3(S_/128, BH_), 256, 65536>>>(q, k);
    attn_pass2<<<dim3(S_/128, BH_), 256, 49152>>>(v, attn);

    gemm128<<<ggrid, 256>>>(attn, Wo, out);
}

// round 2
// speedup vs baseline: 1.0025x; 1.0025x over previous
#include <cuda_runtime.h>
#include <cuda_bf16.h>
#include <math.h>

#define B_  2
#define S_  2048
#define D_  1024
#define H_  16
#define DK  64
#define BH_ (B_*H_)

// ---------------- scratch (static device allocations; no cudaMalloc) ----------------
__device__ float g_q[(size_t)B_*S_*D_];
__device__ float g_k[(size_t)B_*S_*D_];
__device__ float g_v[(size_t)B_*S_*D_];
__device__ float g_attn[(size_t)B_*S_*D_];
__device__ float g_scores[(size_t)BH_*S_*S_];   // 512 MB
__device__ float g_m[BH_*S_];
__device__ float g_z[BH_*S_];

// ---------------- packed fp32x2 helpers (FFMA2 — ptxas never emits these) ----------
union F4U { float4 f4; unsigned long long u[2]; float f[4]; };

__device__ __forceinline__ unsigned long long pk2(float x) {
    unsigned long long r;
    asm("mov.b64 %0, {%1, %1};" : "=l"(r) : "f"(x));
    return r;
}
__device__ __forceinline__ void ffma2(unsigned long long& d,
                                      unsigned long long a, unsigned long long b) {
    asm("fma.rn.f32x2 %0, %1, %2, %0;" : "+l"(d) : "l"(a), "l"(b));
}
__device__ __forceinline__ float2 upk(unsigned long long v) {
    float2 r;
    asm("mov.b64 {%0, %1}, %2;" : "=f"(r.x), "=f"(r.y) : "l"(v));
    return r;
}

// ---------------- generic 128x128 fp32 GEMM: C[M,1024] = A[M,1024] @ W[1024,1024] ----
__global__ __launch_bounds__(256, 2) void gemm128(const float* __restrict__ A,
                                                  const float* __restrict__ W,
                                                  float* __restrict__ C) {
    __shared__ float As[16*128];   // [kk][m]
    __shared__ float Bs[16*128];   // [kk][n]
    const int tid = threadIdx.x;
    const int ty = tid >> 4, tx = tid & 15;
    const int m0 = blockIdx.y * 128, n0 = blockIdx.x * 128;

    // packed accumulators: acc2[ip][j] = (acc[2ip][j], acc[2ip+1][j])
    unsigned long long acc2[4][8];
#pragma unroll
    for (int ip = 0; ip < 4; ip++)
#pragma unroll
        for (int j = 0; j < 8; j++) acc2[ip][j] = 0ULL;

    for (int k0 = 0; k0 < 1024; k0 += 16) {
        // A tile 128x16 -> As[kk][m] (transposed store)
#pragma unroll
        for (int u = 0; u < 2; u++) {
            int idx = tid * 2 + u;         // 0..511
            int m = idx >> 2, c4 = idx & 3;
            float4 v = *(const float4*)&A[(size_t)(m0 + m) * 1024 + k0 + c4 * 4];
            As[(c4 * 4 + 0) * 128 + m] = v.x;
            As[(c4 * 4 + 1) * 128 + m] = v.y;
            As[(c4 * 4 + 2) * 128 + m] = v.z;
            As[(c4 * 4 + 3) * 128 + m] = v.w;
        }
        // B tile 16x128 -> Bs[kk][n] (direct)
#pragma unroll
        for (int u = 0; u < 2; u++) {
            int idx = tid * 2 + u;
            int kk = idx >> 5, n4 = idx & 31;
            *(float4*)&Bs[kk * 128 + n4 * 4] =
                *(const float4*)&W[(size_t)(k0 + kk) * 1024 + n0 + n4 * 4];
        }
        __syncthreads();
#pragma unroll
        for (int kk = 0; kk < 16; kk++) {
            F4U A0, A1, B0, B1;
            A0.f4 = *(const float4*)&As[kk * 128 + ty * 8];
            A1.f4 = *(const float4*)&As[kk * 128 + ty * 8 + 4];
            B0.f4 = *(const float4*)&Bs[kk * 128 + tx * 8];
            B1.f4 = *(const float4*)&Bs[kk * 128 + tx * 8 + 4];
            unsigned long long ap[4] = {A0.u[0], A0.u[1], A1.u[0], A1.u[1]};
            unsigned long long bd[8];
#pragma unroll
            for (int j = 0; j < 4; j++) { bd[j] = pk2(B0.f[j]); bd[4 + j] = pk2(B1.f[j]); }
#pragma unroll
            for (int ip = 0; ip < 4; ip++)
#pragma unroll
                for (int j = 0; j < 8; j++) ffma2(acc2[ip][j], ap[ip], bd[j]);
        }
        __syncthreads();
    }
#pragma unroll
    for (int ip = 0; ip < 4; ip++) {
        float r0[8], r1[8];
#pragma unroll
        for (int j = 0; j < 8; j++) {
            float2 t = upk(acc2[ip][j]);
            r0[j] = t.x; r1[j] = t.y;
        }
        size_t o0 = (size_t)(m0 + ty * 8 + 2 * ip) * 1024 + n0 + tx * 8;
        size_t o1 = o0 + 1024;
        *(float4*)&C[o0]     = make_float4(r0[0], r0[1], r0[2], r0[3]);
        *(float4*)&C[o0 + 4] = make_float4(r0[4], r0[5], r0[6], r0[7]);
        *(float4*)&C[o1]     = make_float4(r1[0], r1[1], r1[2], r1[3]);
        *(float4*)&C[o1 + 4] = make_float4(r1[4], r1[5], r1[6], r1[7]);
    }
}

// ---------------- RoPE (in-place on q and k) ----------------
__global__ void rope_kernel(float* __restrict__ q, float* __restrict__ k,
                            const float* __restrict__ fc, const float* __restrict__ fs) {
    int idx = blockIdx.x * blockDim.x + threadIdx.x;   // B*S*H*32 = 2097152
    int i = idx & 31;
    int h = (idx >> 5) & 15;
    int s = (idx >> 9) & (S_ - 1);
    int b = idx >> 20;
    float c  = fc[s * 32 + i];
    float sn = fs[s * 32 + i];
    size_t base = ((size_t)(b * S_ + s)) * D_ + h * DK + 2 * i;
    float a0 = q[base], a1 = q[base + 1];
    q[base]     = a0 * c - a1 * sn;
    q[base + 1] = a0 * sn + a1 * c;
    a0 = k[base]; a1 = k[base + 1];
    k[base]     = a0 * c - a1 * sn;
    k[base + 1] = a0 * sn + a1 * c;
}

// ---------------- pass 1: scores = QK^T/8 -> scratch, online (m, Z) ----------------
__global__ __launch_bounds__(256, 2) void attn_pass1(const float* __restrict__ q,
                                                     const float* __restrict__ k) {
    extern __shared__ float sm[];
    float* Qs = sm;             // [64][128]  (d-major, transposed)
    float* Ks = sm + 64 * 128;  // [64][128]
    const int tid = threadIdx.x;
    const int ty = tid >> 4, tx = tid & 15;
    const int bh = blockIdx.y, b = bh >> 4, h = bh & 15;
    const int q0 = blockIdx.x * 128;

    // load Q tile transposed
    {
        const float* src = q + ((size_t)(b * S_) + q0) * D_ + h * DK;
#pragma unroll
        for (int u = 0; u < 8; u++) {
            int idx = tid * 8 + u;          // 0..2047 float4s
            int row = idx >> 4, c4 = idx & 15;
            float4 v = *(const float4*)&src[(size_t)row * D_ + c4 * 4];
            Qs[(c4 * 4 + 0) * 128 + row] = v.x;
            Qs[(c4 * 4 + 1) * 128 + row] = v.y;
            Qs[(c4 * 4 + 2) * 128 + row] = v.z;
            Qs[(c4 * 4 + 3) * 128 + row] = v.w;
        }
    }

    float mrow[8], zrow[8];
#pragma unroll
    for (int i = 0; i < 8; i++) { mrow[i] = -1e30f; zrow[i] = 0.f; }

    for (int kt = 0; kt < 16; kt++) {
        const int k0 = kt * 128;
        __syncthreads();   // previous tile's readers done (also fences Q stores on iter 0)
        {
            const float* src = k + ((size_t)(b * S_) + k0) * D_ + h * DK;
#pragma unroll
            for (int u = 0; u < 8; u++) {
                int idx = tid * 8 + u;
                int row = idx >> 4, c4 = idx & 15;
                float4 v = *(const float4*)&src[(size_t)row * D_ + c4 * 4];
                Ks[(c4 * 4 + 0) * 128 + row] = v.x;
                Ks[(c4 * 4 + 1) * 128 + row] = v.y;
                Ks[(c4 * 4 + 2) * 128 + row] = v.z;
                Ks[(c4 * 4 + 3) * 128 + row] = v.w;
            }
        }
        __syncthreads();

        unsigned long long acc2[4][8];
#pragma unroll
        for (int ip = 0; ip < 4; ip++)
#pragma unroll
            for (int j = 0; j < 8; j++) acc2[ip][j] = 0ULL;

#pragma unroll 4
        for (int d = 0; d < 64; d++) {
            F4U A0, A1, B0, B1;
            A0.f4 = *(const float4*)&Qs[d * 128 + ty * 8];
            A1.f4 = *(const float4*)&Qs[d * 128 + ty * 8 + 4];
            B0.f4 = *(const float4*)&Ks[d * 128 + tx * 8];
            B1.f4 = *(const float4*)&Ks[d * 128 + tx * 8 + 4];
            unsigned long long ap[4] = {A0.u[0], A0.u[1], A1.u[0], A1.u[1]};
            unsigned long long bd[8];
#pragma unroll
            for (int j = 0; j < 4; j++) { bd[j] = pk2(B0.f[j]); bd[4 + j] = pk2(B1.f[j]); }
#pragma unroll
            for (int ip = 0; ip < 4; ip++)
#pragma unroll
                for (int j = 0; j < 8; j++) ffma2(acc2[ip][j], ap[ip], bd[j]);
        }

        // unpack (with 1/8 scale), then identical epilogue as before
        float acc[8][8];
#pragma unroll
        for (int ip = 0; ip < 4; ip++)
#pragma unroll
            for (int j = 0; j < 8; j++) {
                float2 t = upk(acc2[ip][j]);
                acc[2 * ip][j]     = t.x * 0.125f;
                acc[2 * ip + 1][j] = t.y * 0.125f;
            }

#pragma unroll
        for (int i = 0; i < 8; i++) {
            size_t off = ((size_t)bh * S_ + q0 + ty * 8 + i) * S_ + k0 + tx * 8;
            *(float4*)&g_scores[off]     = make_float4(acc[i][0], acc[i][1], acc[i][2], acc[i][3]);
            *(float4*)&g_scores[off + 4] = make_float4(acc[i][4], acc[i][5], acc[i][6], acc[i][7]);

            float lm = acc[i][0];
#pragma unroll
            for (int j = 1; j < 8; j++) lm = fmaxf(lm, acc[i][j]);
#pragma unroll
            for (int o = 8; o; o >>= 1) lm = fmaxf(lm, __shfl_xor_sync(0xffffffffu, lm, o));
            float mn = fmaxf(mrow[i], lm);
            float ls = 0.f;
#pragma unroll
            for (int j = 0; j < 8; j++) ls += __expf(acc[i][j] - mn);
#pragma unroll
            for (int o = 8; o; o >>= 1) ls += __shfl_xor_sync(0xffffffffu, ls, o);
            zrow[i] = zrow[i] * __expf(mrow[i] - mn) + ls;
            mrow[i] = mn;
        }
    }

    if (tx == 0) {
#pragma unroll
        for (int i = 0; i < 8; i++) {
            int qg = q0 + ty * 8 + i;
            g_m[bh * S_ + qg] = mrow[i];
            g_z[bh * S_ + qg] = zrow[i];
        }
    }
}

// ---------------- pass 2: t = exp(softmax(s)), out = (t @ V) / sum(t) ----------------
__global__ __launch_bounds__(256, 2) void attn_pass2(const float* __restrict__ v,
                                                     float* __restrict__ attn) {
    extern __shared__ float sm[];
    float* Ts = sm;             // [64 k][128 q] floats, XOR-swizzled float4 slots
    float* Vs = sm + 64 * 128;  // [64 k][64 dv]
    float4* Ts4 = (float4*)Ts;
    const int tid = threadIdx.x;
    const int ty = tid >> 4, tx = tid & 15;
    const int bh = blockIdx.y, b = bh >> 4, h = bh & 15;
    const int q0 = blockIdx.x * 128;

    float mq[8], iz[8];
#pragma unroll
    for (int i = 0; i < 8; i++) {
        int qg = q0 + ty * 8 + i;
        mq[i] = g_m[bh * S_ + qg];
        iz[i] = 1.0f / g_z[bh * S_ + qg];
    }

    // packed accumulators along i: acc2[ip][j] = (acc[2ip][j], acc[2ip+1][j]), j in 0..3
    unsigned long long acc2[4][4];
    float tsum[8];
#pragma unroll
    for (int i = 0; i < 8; i++) tsum[i] = 0.f;
#pragma unroll
    for (int ip = 0; ip < 4; ip++)
#pragma unroll
        for (int j = 0; j < 4; j++) acc2[ip][j] = 0ULL;

    for (int kt = 0; kt < 32; kt++) {
        const int k0 = kt * 64;
        __syncthreads();   // previous tile readers done
        // V tile 64x64
        {
            const float* src = v + ((size_t)(b * S_) + k0) * D_ + h * DK;
#pragma unroll
            for (int u = 0; u < 4; u++) {
                int idx = tid * 4 + u;          // 0..1023 float4s
                int row = idx >> 4, c4 = idx & 15;
                *(float4*)&Vs[row * 64 + c4 * 4] =
                    *(const float4*)&src[(size_t)row * D_ + c4 * 4];
            }
        }
        // t = exp(exp(s - m)/Z)
        float tv[8][4];
#pragma unroll
        for (int i = 0; i < 8; i++) {
            size_t off = ((size_t)bh * S_ + q0 + ty * 8 + i) * S_ + k0 + tx * 4;
            float4 s4 = *(const float4*)&g_scores[off];
            tv[i][0] = __expf(__expf(s4.x - mq[i]) * iz[i]);
            tv[i][1] = __expf(__expf(s4.y - mq[i]) * iz[i]);
            tv[i][2] = __expf(__expf(s4.z - mq[i]) * iz[i]);
            tv[i][3] = __expf(__expf(s4.w - mq[i]) * iz[i]);
            tsum[i] += tv[i][0] + tv[i][1] + tv[i][2] + tv[i][3];
        }
        // store t transposed into Ts[k][q] with swizzle slot = q4 ^ (k>>2)
#pragma unroll
        for (int p = 0; p < 2; p++)
#pragma unroll
            for (int j = 0; j < 4; j++) {
                int kk = tx * 4 + j;
                int slot = (ty * 2 + p) ^ tx;    // tx == kk>>2
                Ts4[kk * 32 + slot] =
                    make_float4(tv[p * 4 + 0][j], tv[p * 4 + 1][j],
                                tv[p * 4 + 2][j], tv[p * 4 + 3][j]);
            }
        __syncthreads();

#pragma unroll 4
        for (int kk = 0; kk < 64; kk++) {
            F4U T0, T1, V4;
            T0.f4 = Ts4[kk * 32 + ((ty * 2) ^ (kk >> 2))];
            T1.f4 = Ts4[kk * 32 + ((ty * 2 + 1) ^ (kk >> 2))];
            V4.f4 = *(const float4*)&Vs[kk * 64 + tx * 4];
            unsigned long long tp[4] = {T0.u[0], T0.u[1], T1.u[0], T1.u[1]};
            unsigned long long vd[4];
#pragma unroll
            for (int j = 0; j < 4; j++) vd[j] = pk2(V4.f[j]);
#pragma unroll
            for (int ip = 0; ip < 4; ip++)
#pragma unroll
                for (int j = 0; j < 4; j++) ffma2(acc2[ip][j], tp[ip], vd[j]);
        }
    }

#pragma unroll
    for (int i = 0; i < 8; i++)
#pragma unroll
        for (int o = 8; o; o >>= 1) tsum[i] += __shfl_xor_sync(0xffffffffu, tsum[i], o);

    float accf[8][4];
#pragma unroll
    for (int ip = 0; ip < 4; ip++)
#pragma unroll
        for (int j = 0; j < 4; j++) {
            float2 t = upk(acc2[ip][j]);
            accf[2 * ip][j]     = t.x;
            accf[2 * ip + 1][j] = t.y;
        }

#pragma unroll
    for (int i = 0; i < 8; i++) {
        float r = 1.0f / tsum[i];
        size_t off = ((size_t)(b * S_) + q0 + ty * 8 + i) * D_ + h * DK + tx * 4;
        *(float4*)&attn[off] =
            make_float4(accf[i][0] * r, accf[i][1] * r, accf[i][2] * r, accf[i][3] * r);
    }
}

// ---------------- launch ----------------
extern "C" void kernel_launch(void* const* d_in, const int* in_sizes, int n_in,
                              void* d_out, int out_size) {
    const float* x  = (const float*)d_in[0];
    const float* fc = (const float*)d_in[1];
    const float* fs = (const float*)d_in[2];
    const float* Wq = (const float*)d_in[3];
    const float* Wk = (const float*)d_in[4];
    const float* Wv = (const float*)d_in[5];
    const float* Wo = (const float*)d_in[6];
    float* out = (float*)d_out;

    float *q, *k, *v, *attn;
    cudaGetSymbolAddress((void**)&q, g_q);
    cudaGetSymbolAddress((void**)&k, g_k);
    cudaGetSymbolAddress((void**)&v, g_v);
    cudaGetSymbolAddress((void**)&attn, g_attn);

    cudaFuncSetAttribute(attn_pass1, cudaFuncAttributeMaxDynamicSharedMemorySize, 65536);
    cudaFuncSetAttribute(attn_pass2, cudaFuncAttributeMaxDynamicSharedMemorySize, 49152);

    dim3 ggrid(8, 32);                         // 1024/128 x 4096/128
    gemm128<<<ggrid, 256>>>(x, Wq, q);
    gemm128<<<ggrid, 256>>>(x, Wk, k);
    gemm128<<<ggrid, 256>>>(x, Wv, v);

    rope_kernel<<<(B_*S_*H_*(DK/2)) / 256, 256>>>(q, k, fc, fs);

    attn_pass1<<<dim3(S_/128, BH_), 256, 65536>>>(q, k);
    attn_pass2<<<dim3(S_/128, BH_), 256, 49152>>>(v, attn);

    gemm128<<<ggrid, 256>>>(attn, Wo, out);
}

// round 4
// speedup vs baseline: 1.3172x; 1.3139x over previous
#include <cuda_runtime.h>
#include <cuda_bf16.h>
#include <math.h>

#define B_  2
#define S_  2048
#define D_  1024
#define H_  16
#define DK  64
#define BH_ (B_*H_)
#define MS_ (B_*S_)          // 4096 rows

// ---------------- scratch (static device arrays; no cudaMalloc) ----------------
__device__ float g_q[(size_t)MS_*D_];
__device__ float g_k[(size_t)MS_*D_];
__device__ float g_v[(size_t)MS_*D_];
__device__ float g_attn[(size_t)MS_*D_];
__device__ float g_scores[(size_t)BH_*S_*S_];   // 512 MB
__device__ float g_m[BH_*S_];
__device__ float g_z[BH_*S_];
// bf16 split buffers
__device__ __nv_bfloat16 g_xhi[(size_t)MS_*D_];
__device__ __nv_bfloat16 g_xlo[(size_t)MS_*D_];
__device__ __nv_bfloat16 g_ahi[(size_t)MS_*D_];
__device__ __nv_bfloat16 g_alo[(size_t)MS_*D_];
__device__ __nv_bfloat16 g_wthi[4][(size_t)D_*D_];   // W^T hi ([n][k], k contiguous)
__device__ __nv_bfloat16 g_wtlo[4][(size_t)D_*D_];

// ================= helpers =================
__device__ __forceinline__ unsigned smem_u32(const void* p) {
    unsigned a;
    asm("{ .reg .u64 t; cvta.to.shared.u64 t, %1; cvt.u32.u64 %0, t; }" : "=r"(a) : "l"(p));
    return a;
}
__device__ __forceinline__ void cp16(unsigned saddr, const void* gaddr) {
    asm volatile("cp.async.cg.shared.global [%0], [%1], 16;" :: "r"(saddr), "l"(gaddr));
}
__device__ __forceinline__ void cp_commit() { asm volatile("cp.async.commit_group;"); }
template <int N>
__device__ __forceinline__ void cp_wait() { asm volatile("cp.async.wait_group %0;" :: "n"(N)); }

__device__ __forceinline__ void mma16816(float* c, const unsigned* a, unsigned b0, unsigned b1) {
    asm volatile("mma.sync.aligned.m16n8k16.row.col.f32.bf16.bf16.f32 "
                 "{%0,%1,%2,%3}, {%4,%5,%6,%7}, {%8,%9}, {%0,%1,%2,%3};"
                 : "+f"(c[0]), "+f"(c[1]), "+f"(c[2]), "+f"(c[3])
                 : "r"(a[0]), "r"(a[1]), "r"(a[2]), "r"(a[3]), "r"(b0), "r"(b1));
}

// ================= split kernels =================
__global__ void splitX(const float* __restrict__ X, __nv_bfloat16* __restrict__ hi,
                       __nv_bfloat16* __restrict__ lo) {
    int i = blockIdx.x * 256 + threadIdx.x;
    float v = X[i];
    __nv_bfloat16 h = __float2bfloat16(v);
    hi[i] = h;
    lo[i] = __float2bfloat16(v - __bfloat162float(h));
}

// W[k][n] (row-major 1024x1024) -> WT hi/lo [n][k]
__global__ void splitWT(const float* __restrict__ W, __nv_bfloat16* __restrict__ hi,
                        __nv_bfloat16* __restrict__ lo) {
    __shared__ float t[32][33];
    int bx = blockIdx.x * 32, by = blockIdx.y * 32;   // bx: n, by: k
    int tx = threadIdx.x & 31, ty = threadIdx.x >> 5;
#pragma unroll
    for (int i = 0; i < 32; i += 8)
        t[ty + i][tx] = W[(size_t)(by + ty + i) * 1024 + bx + tx];
    __syncthreads();
#pragma unroll
    for (int i = 0; i < 32; i += 8) {
        float v = t[tx][ty + i];
        __nv_bfloat16 h = __float2bfloat16(v);
        size_t o = (size_t)(bx + ty + i) * 1024 + by + tx;
        hi[o] = h;
        lo[o] = __float2bfloat16(v - __bfloat162float(h));
    }
}

// ================= bf16 split GEMM via mma.sync =================
// C[4096,1024] = A @ W ; A split (Ahi,Alo)[m][k], W^T split (Bhi,Blo)[n][k]
// tile 128x128x32, 8 warps (4m x 2n), warp tile 32x64
#define SA    40                    // smem row stride in bf16 (80 B, conflict-free)
#define TILEB (128 * SA * 2)        // 10240 B per tile
#define BUFB  (4 * TILEB)           // Ah, Al, Bh, Bl
#define GSMEM (2 * BUFB)            // double buffered: 81920 B

__global__ __launch_bounds__(256, 1) void gemm_mma(const __nv_bfloat16* __restrict__ Ahi,
                                                   const __nv_bfloat16* __restrict__ Alo,
                                                   const __nv_bfloat16* __restrict__ Bhi,
                                                   const __nv_bfloat16* __restrict__ Blo,
                                                   float* __restrict__ C) {
    extern __shared__ char smc[];
    const int tid = threadIdx.x, lane = tid & 31, wid = tid >> 5;
    const int wm = wid & 3, wn = wid >> 2;          // 4 x 2 warp grid
    const int grp = lane >> 2, qid = lane & 3;
    const int m0 = blockIdx.y * 128, n0 = blockIdx.x * 128;
    const unsigned sb = smem_u32(smc);

    const __nv_bfloat16* srcs[4] = {Ahi, Alo, Bhi, Blo};
    const int r0s[4] = {m0, m0, n0, n0};

    float acc[2][8][4];
#pragma unroll
    for (int mt = 0; mt < 2; mt++)
#pragma unroll
        for (int nt = 0; nt < 8; nt++)
#pragma unroll
            for (int e = 0; e < 4; e++) acc[mt][nt][e] = 0.f;

    // ---- prefetch chunk 0 into buf 0 ----
    {
        const int k0 = 0;
#pragma unroll
        for (int t = 0; t < 4; t++) {
#pragma unroll
            for (int u = 0; u < 2; u++) {
                int idx = tid * 2 + u;               // 0..511
                int row = idx >> 2, seg = idx & 3;
                cp16(sb + t * TILEB + row * 80 + seg * 16,
                     srcs[t] + (size_t)(r0s[t] + row) * 1024 + k0 + seg * 8);
            }
        }
        cp_commit();
    }

    for (int ch = 0; ch < 32; ch++) {
        const int buf = ch & 1;
        if (ch < 31) {
            const int k0 = (ch + 1) * 32, nbuf = (ch + 1) & 1;
#pragma unroll
            for (int t = 0; t < 4; t++) {
#pragma unroll
                for (int u = 0; u < 2; u++) {
                    int idx = tid * 2 + u;
                    int row = idx >> 2, seg = idx & 3;
                    cp16(sb + nbuf * BUFB + t * TILEB + row * 80 + seg * 16,
                         srcs[t] + (size_t)(r0s[t] + row) * 1024 + k0 + seg * 8);
                }
            }
            cp_commit();
            cp_wait<1>();
        } else {
            cp_wait<0>();
        }
        __syncthreads();

        const __nv_bfloat16* Ah = (const __nv_bfloat16*)(smc + buf * BUFB);
        const __nv_bfloat16* Al = Ah + 128 * SA;
        const __nv_bfloat16* Bh = Ah + 2 * 128 * SA;
        const __nv_bfloat16* Bl = Ah + 3 * 128 * SA;

#pragma unroll
        for (int kk = 0; kk < 32; kk += 16) {
            unsigned afh[2][4], afl[2][4];
#pragma unroll
            for (int mt = 0; mt < 2; mt++) {
                int r = wm * 32 + mt * 16 + grp;
                afh[mt][0] = *(const unsigned*)&Ah[r * SA + kk + qid * 2];
                afh[mt][1] = *(const unsigned*)&Ah[(r + 8) * SA + kk + qid * 2];
                afh[mt][2] = *(const unsigned*)&Ah[r * SA + kk + 8 + qid * 2];
                afh[mt][3] = *(const unsigned*)&Ah[(r + 8) * SA + kk + 8 + qid * 2];
                afl[mt][0] = *(const unsigned*)&Al[r * SA + kk + qid * 2];
                afl[mt][1] = *(const unsigned*)&Al[(r + 8) * SA + kk + qid * 2];
                afl[mt][2] = *(const unsigned*)&Al[r * SA + kk + 8 + qid * 2];
                afl[mt][3] = *(const unsigned*)&Al[(r + 8) * SA + kk + 8 + qid * 2];
            }
#pragma unroll
            for (int nt = 0; nt < 8; nt++) {
                int c = wn * 64 + nt * 8 + grp;
                unsigned bh0 = *(const unsigned*)&Bh[c * SA + kk + qid * 2];
                unsigned bh1 = *(const unsigned*)&Bh[c * SA + kk + 8 + qid * 2];
                unsigned bl0 = *(const unsigned*)&Bl[c * SA + kk + qid * 2];
                unsigned bl1 = *(const unsigned*)&Bl[c * SA + kk + 8 + qid * 2];
#pragma unroll
                for (int mt = 0; mt < 2; mt++) {
                    mma16816(acc[mt][nt], afh[mt], bh0, bh1);
                    mma16816(acc[mt][nt], afh[mt], bl0, bl1);
                    mma16816(acc[mt][nt], afl[mt], bh0, bh1);
                }
            }
        }
        __syncthreads();
    }

    // epilogue
#pragma unroll
    for (int mt = 0; mt < 2; mt++) {
        int r = m0 + wm * 32 + mt * 16 + grp;
#pragma unroll
        for (int nt = 0; nt < 8; nt++) {
            int c = n0 + wn * 64 + nt * 8 + qid * 2;
            *(float2*)&C[(size_t)r * 1024 + c]       = make_float2(acc[mt][nt][0], acc[mt][nt][1]);
            *(float2*)&C[(size_t)(r + 8) * 1024 + c] = make_float2(acc[mt][nt][2], acc[mt][nt][3]);
        }
    }
}

// ================= RoPE =================
__global__ void rope_kernel(float* __restrict__ q, float* __restrict__ k,
                            const float* __restrict__ fc, const float* __restrict__ fs) {
    int idx = blockIdx.x * blockDim.x + threadIdx.x;
    int i = idx & 31;
    int h = (idx >> 5) & 15;
    int s = (idx >> 9) & (S_ - 1);
    int b = idx >> 20;
    float c  = fc[s * 32 + i];
    float sn = fs[s * 32 + i];
    size_t base = ((size_t)(b * S_ + s)) * D_ + h * DK + 2 * i;
    float a0 = q[base], a1 = q[base + 1];
    q[base]     = a0 * c - a1 * sn;
    q[base + 1] = a0 * sn + a1 * c;
    a0 = k[base]; a1 = k[base + 1];
    k[base]     = a0 * c - a1 * sn;
    k[base + 1] = a0 * sn + a1 * c;
}

// ---------------- packed fp32x2 helpers (attention passes) ----------
union F4U { float4 f4; unsigned long long u[2]; float f[4]; };
__device__ __forceinline__ unsigned long long pk2(float x) {
    unsigned long long r;
    asm("mov.b64 %0, {%1, %1};" : "=l"(r) : "f"(x));
    return r;
}
__device__ __forceinline__ void ffma2(unsigned long long& d,
                                      unsigned long long a, unsigned long long b) {
    asm("fma.rn.f32x2 %0, %1, %2, %0;" : "+l"(d) : "l"(a), "l"(b));
}
__device__ __forceinline__ float2 upk(unsigned long long v) {
    float2 r;
    asm("mov.b64 {%0, %1}, %2;" : "=f"(r.x), "=f"(r.y) : "l"(v));
    return r;
}

// ---------------- pass 1: scores = QK^T/8 -> scratch, online (m, Z) ----------------
__global__ __launch_bounds__(256, 2) void attn_pass1(const float* __restrict__ q,
                                                     const float* __restrict__ k) {
    extern __shared__ float sm[];
    float* Qs = sm;
    float* Ks = sm + 64 * 128;
    const int tid = threadIdx.x;
    const int ty = tid >> 4, tx = tid & 15;
    const int bh = blockIdx.y, b = bh >> 4, h = bh & 15;
    const int q0 = blockIdx.x * 128;

    {
        const float* src = q + ((size_t)(b * S_) + q0) * D_ + h * DK;
#pragma unroll
        for (int u = 0; u < 8; u++) {
            int idx = tid * 8 + u;
            int row = idx >> 4, c4 = idx & 15;
            float4 v = *(const float4*)&src[(size_t)row * D_ + c4 * 4];
            Qs[(c4 * 4 + 0) * 128 + row] = v.x;
            Qs[(c4 * 4 + 1) * 128 + row] = v.y;
            Qs[(c4 * 4 + 2) * 128 + row] = v.z;
            Qs[(c4 * 4 + 3) * 128 + row] = v.w;
        }
    }

    float mrow[8], zrow[8];
#pragma unroll
    for (int i = 0; i < 8; i++) { mrow[i] = -1e30f; zrow[i] = 0.f; }

    for (int kt = 0; kt < 16; kt++) {
        const int k0 = kt * 128;
        __syncthreads();
        {
            const float* src = k + ((size_t)(b * S_) + k0) * D_ + h * DK;
#pragma unroll
            for (int u = 0; u < 8; u++) {
                int idx = tid * 8 + u;
                int row = idx >> 4, c4 = idx & 15;
                float4 v = *(const float4*)&src[(size_t)row * D_ + c4 * 4];
                Ks[(c4 * 4 + 0) * 128 + row] = v.x;
                Ks[(c4 * 4 + 1) * 128 + row] = v.y;
                Ks[(c4 * 4 + 2) * 128 + row] = v.z;
                Ks[(c4 * 4 + 3) * 128 + row] = v.w;
            }
        }
        __syncthreads();

        unsigned long long acc2[4][8];
#pragma unroll
        for (int ip = 0; ip < 4; ip++)
#pragma unroll
            for (int j = 0; j < 8; j++) acc2[ip][j] = 0ULL;

#pragma unroll 4
        for (int d = 0; d < 64; d++) {
            F4U A0, A1, B0, B1;
            A0.f4 = *(const float4*)&Qs[d * 128 + ty * 8];
            A1.f4 = *(const float4*)&Qs[d * 128 + ty * 8 + 4];
            B0.f4 = *(const float4*)&Ks[d * 128 + tx * 8];
            B1.f4 = *(const float4*)&Ks[d * 128 + tx * 8 + 4];
            unsigned long long ap[4] = {A0.u[0], A0.u[1], A1.u[0], A1.u[1]};
            unsigned long long bd[8];
#pragma unroll
            for (int j = 0; j < 4; j++) { bd[j] = pk2(B0.f[j]); bd[4 + j] = pk2(B1.f[j]); }
#pragma unroll
            for (int ip = 0; ip < 4; ip++)
#pragma unroll
                for (int j = 0; j < 8; j++) ffma2(acc2[ip][j], ap[ip], bd[j]);
        }

        float acc[8][8];
#pragma unroll
        for (int ip = 0; ip < 4; ip++)
#pragma unroll
            for (int j = 0; j < 8; j++) {
                float2 t = upk(acc2[ip][j]);
                acc[2 * ip][j]     = t.x * 0.125f;
                acc[2 * ip + 1][j] = t.y * 0.125f;
            }

#pragma unroll
        for (int i = 0; i < 8; i++) {
            size_t off = ((size_t)bh * S_ + q0 + ty * 8 + i) * S_ + k0 + tx * 8;
            *(float4*)&g_scores[off]     = make_float4(acc[i][0], acc[i][1], acc[i][2], acc[i][3]);
            *(float4*)&g_scores[off + 4] = make_float4(acc[i][4], acc[i][5], acc[i][6], acc[i][7]);

            float lm = acc[i][0];
#pragma unroll
            for (int j = 1; j < 8; j++) lm = fmaxf(lm, acc[i][j]);
#pragma unroll
            for (int o = 8; o; o >>= 1) lm = fmaxf(lm, __shfl_xor_sync(0xffffffffu, lm, o));
            float mn = fmaxf(mrow[i], lm);
            float ls = 0.f;
#pragma unroll
            for (int j = 0; j < 8; j++) ls += __expf(acc[i][j] - mn);
#pragma unroll
            for (int o = 8; o; o >>= 1) ls += __shfl_xor_sync(0xffffffffu, ls, o);
            zrow[i] = zrow[i] * __expf(mrow[i] - mn) + ls;
            mrow[i] = mn;
        }
    }

    if (tx == 0) {
#pragma unroll
        for (int i = 0; i < 8; i++) {
            int qg = q0 + ty * 8 + i;
            g_m[bh * S_ + qg] = mrow[i];
            g_z[bh * S_ + qg] = zrow[i];
        }
    }
}

// ---------------- pass 2: t = exp(softmax(s)), out = (t @ V) / sum(t) ----------------
__global__ __launch_bounds__(256, 2) void attn_pass2(const float* __restrict__ v,
                                                     float* __restrict__ attn) {
    extern __shared__ float sm[];
    float* Ts = sm;
    float* Vs = sm + 64 * 128;
    float4* Ts4 = (float4*)Ts;
    const int tid = threadIdx.x;
    const int ty = tid >> 4, tx = tid & 15;
    const int bh = blockIdx.y, b = bh >> 4, h = bh & 15;
    const int q0 = blockIdx.x * 128;

    float mq[8], iz[8];
#pragma unroll
    for (int i = 0; i < 8; i++) {
        int qg = q0 + ty * 8 + i;
        mq[i] = g_m[bh * S_ + qg];
        iz[i] = 1.0f / g_z[bh * S_ + qg];
    }

    unsigned long long acc2[4][4];
    float tsum[8];
#pragma unroll
    for (int i = 0; i < 8; i++) tsum[i] = 0.f;
#pragma unroll
    for (int ip = 0; ip < 4; ip++)
#pragma unroll
        for (int j = 0; j < 4; j++) acc2[ip][j] = 0ULL;

    for (int kt = 0; kt < 32; kt++) {
        const int k0 = kt * 64;
        __syncthreads();
        {
            const float* src = v + ((size_t)(b * S_) + k0) * D_ + h * DK;
#pragma unroll
            for (int u = 0; u < 4; u++) {
                int idx = tid * 4 + u;
                int row = idx >> 4, c4 = idx & 15;
                *(float4*)&Vs[row * 64 + c4 * 4] =
                    *(const float4*)&src[(size_t)row * D_ + c4 * 4];
            }
        }
        float tv[8][4];
#pragma unroll
        for (int i = 0; i < 8; i++) {
            size_t off = ((size_t)bh * S_ + q0 + ty * 8 + i) * S_ + k0 + tx * 4;
            float4 s4 = *(const float4*)&g_scores[off];
            tv[i][0] = __expf(__expf(s4.x - mq[i]) * iz[i]);
            tv[i][1] = __expf(__expf(s4.y - mq[i]) * iz[i]);
            tv[i][2] = __expf(__expf(s4.z - mq[i]) * iz[i]);
            tv[i][3] = __expf(__expf(s4.w - mq[i]) * iz[i]);
            tsum[i] += tv[i][0] + tv[i][1] + tv[i][2] + tv[i][3];
        }
#pragma unroll
        for (int p = 0; p < 2; p++)
#pragma unroll
            for (int j = 0; j < 4; j++) {
                int kk = tx * 4 + j;
                int slot = (ty * 2 + p) ^ tx;
                Ts4[kk * 32 + slot] =
                    make_float4(tv[p * 4 + 0][j], tv[p * 4 + 1][j],
                                tv[p * 4 + 2][j], tv[p * 4 + 3][j]);
            }
        __syncthreads();

#pragma unroll 4
        for (int kk = 0; kk < 64; kk++) {
            F4U T0, T1, V4;
            T0.f4 = Ts4[kk * 32 + ((ty * 2) ^ (kk >> 2))];
            T1.f4 = Ts4[kk * 32 + ((ty * 2 + 1) ^ (kk >> 2))];
            V4.f4 = *(const float4*)&Vs[kk * 64 + tx * 4];
            unsigned long long tp[4] = {T0.u[0], T0.u[1], T1.u[0], T1.u[1]};
            unsigned long long vd[4];
#pragma unroll
            for (int j = 0; j < 4; j++) vd[j] = pk2(V4.f[j]);
#pragma unroll
            for (int ip = 0; ip < 4; ip++)
#pragma unroll
                for (int j = 0; j < 4; j++) ffma2(acc2[ip][j], tp[ip], vd[j]);
        }
    }

#pragma unroll
    for (int i = 0; i < 8; i++)
#pragma unroll
        for (int o = 8; o; o >>= 1) tsum[i] += __shfl_xor_sync(0xffffffffu, tsum[i], o);

    float accf[8][4];
#pragma unroll
    for (int ip = 0; ip < 4; ip++)
#pragma unroll
        for (int j = 0; j < 4; j++) {
            float2 t = upk(acc2[ip][j]);
            accf[2 * ip][j]     = t.x;
            accf[2 * ip + 1][j] = t.y;
        }

#pragma unroll
    for (int i = 0; i < 8; i++) {
        float r = 1.0f / tsum[i];
        size_t off = ((size_t)(b * S_) + q0 + ty * 8 + i) * D_ + h * DK + tx * 4;
        *(float4*)&attn[off] =
            make_float4(accf[i][0] * r, accf[i][1] * r, accf[i][2] * r, accf[i][3] * r);
    }
}

// ---------------- launch ----------------
extern "C" void kernel_launch(void* const* d_in, const int* in_sizes, int n_in,
                              void* d_out, int out_size) {
    const float* x  = (const float*)d_in[0];
    const float* fc = (const float*)d_in[1];
    const float* fs = (const float*)d_in[2];
    const float* W[4] = {(const float*)d_in[3], (const float*)d_in[4],
                         (const float*)d_in[5], (const float*)d_in[6]};
    float* out = (float*)d_out;

    float *q, *k, *v, *attn;
    __nv_bfloat16 *xhi, *xlo, *ahi, *alo, *wthi, *wtlo;
    cudaGetSymbolAddress((void**)&q, g_q);
    cudaGetSymbolAddress((void**)&k, g_k);
    cudaGetSymbolAddress((void**)&v, g_v);
    cudaGetSymbolAddress((void**)&attn, g_attn);
    cudaGetSymbolAddress((void**)&xhi, g_xhi);
    cudaGetSymbolAddress((void**)&xlo, g_xlo);
    cudaGetSymbolAddress((void**)&ahi, g_ahi);
    cudaGetSymbolAddress((void**)&alo, g_alo);
    cudaGetSymbolAddress((void**)&wthi, g_wthi);
    cudaGetSymbolAddress((void**)&wtlo, g_wtlo);

    cudaFuncSetAttribute(gemm_mma, cudaFuncAttributeMaxDynamicSharedMemorySize, GSMEM);
    cudaFuncSetAttribute(attn_pass1, cudaFuncAttributeMaxDynamicSharedMemorySize, 65536);
    cudaFuncSetAttribute(attn_pass2, cudaFuncAttributeMaxDynamicSharedMemorySize, 49152);

    // splits
    splitX<<<(MS_ * D_) / 256, 256>>>(x, xhi, xlo);
    for (int i = 0; i < 4; i++)
        splitWT<<<dim3(32, 32), 256>>>(W[i], wthi + (size_t)i * D_ * D_,
                                       wtlo + (size_t)i * D_ * D_);

    dim3 ggrid(8, 32);   // n-blocks x m-blocks
    gemm_mma<<<ggrid, 256, GSMEM>>>(xhi, xlo, wthi + 0 * (size_t)D_ * D_,
                                    wtlo + 0 * (size_t)D_ * D_, q);
    gemm_mma<<<ggrid, 256, GSMEM>>>(xhi, xlo, wthi + 1 * (size_t)D_ * D_,
                                    wtlo + 1 * (size_t)D_ * D_, k);
    gemm_mma<<<ggrid, 256, GSMEM>>>(xhi, xlo, wthi + 2 * (size_t)D_ * D_,
                                    wtlo + 2 * (size_t)D_ * D_, v);

    rope_kernel<<<(B_ * S_ * H_ * (DK / 2)) / 256, 256>>>(q, k, fc, fs);

    attn_pass1<<<dim3(S_ / 128, BH_), 256, 65536>>>(q, k);
    attn_pass2<<<dim3(S_ / 128, BH_), 256, 49152>>>(v, attn);

    splitX<<<(MS_ * D_) / 256, 256>>>(attn, ahi, alo);
    gemm_mma<<<ggrid, 256, GSMEM>>>(ahi, alo, wthi + 3 * (size_t)D_ * D_,
                                    wtlo + 3 * (size_t)D_ * D_, out);
}

// round 5
// speedup vs baseline: 1.8122x; 1.3758x over previous
#include <cuda_runtime.h>
#include <cuda_bf16.h>
#include <math.h>

#define B_  2
#define S_  2048
#define D_  1024
#define H_  16
#define DK  64
#define BH_ (B_*H_)
#define MS_ (B_*S_)          // 4096 rows

// ---------------- scratch (static device arrays; no cudaMalloc) ----------------
__device__ float g_q[(size_t)MS_*D_];
__device__ float g_k[(size_t)MS_*D_];
__device__ float g_v[(size_t)MS_*D_];
__device__ float g_attn[(size_t)MS_*D_];
__device__ float g_scores[(size_t)BH_*S_*S_];   // stores u = exp(s/8); 512 MB
__device__ float g_z[BH_*S_];
// bf16 split buffers
__device__ __nv_bfloat16 g_xhi[(size_t)MS_*D_];
__device__ __nv_bfloat16 g_xlo[(size_t)MS_*D_];
__device__ __nv_bfloat16 g_ahi[(size_t)MS_*D_];
__device__ __nv_bfloat16 g_alo[(size_t)MS_*D_];
__device__ __nv_bfloat16 g_wthi[4][(size_t)D_*D_];   // W^T hi ([n][k])
__device__ __nv_bfloat16 g_wtlo[4][(size_t)D_*D_];
// roped q/k splits ([b][s][h][dk]) and transposed V splits ([b][h][dk][s])
__device__ __nv_bfloat16 g_qh[(size_t)MS_*D_];
__device__ __nv_bfloat16 g_ql[(size_t)MS_*D_];
__device__ __nv_bfloat16 g_kh[(size_t)MS_*D_];
__device__ __nv_bfloat16 g_kl[(size_t)MS_*D_];
__device__ __nv_bfloat16 g_vth[(size_t)BH_*DK*S_];
__device__ __nv_bfloat16 g_vtl[(size_t)BH_*DK*S_];

// ================= helpers =================
__device__ __forceinline__ unsigned smem_u32(const void* p) {
    unsigned a;
    asm("{ .reg .u64 t; cvta.to.shared.u64 t, %1; cvt.u32.u64 %0, t; }" : "=r"(a) : "l"(p));
    return a;
}
__device__ __forceinline__ void cp16(unsigned saddr, const void* gaddr) {
    asm volatile("cp.async.cg.shared.global [%0], [%1], 16;" :: "r"(saddr), "l"(gaddr));
}
__device__ __forceinline__ void cp_commit() { asm volatile("cp.async.commit_group;"); }
template <int N>
__device__ __forceinline__ void cp_wait() { asm volatile("cp.async.wait_group %0;" :: "n"(N)); }

__device__ __forceinline__ void mma16816(float* c, const unsigned* a, unsigned b0, unsigned b1) {
    asm volatile("mma.sync.aligned.m16n8k16.row.col.f32.bf16.bf16.f32 "
                 "{%0,%1,%2,%3}, {%4,%5,%6,%7}, {%8,%9}, {%0,%1,%2,%3};"
                 : "+f"(c[0]), "+f"(c[1]), "+f"(c[2]), "+f"(c[3])
                 : "r"(a[0]), "r"(a[1]), "r"(a[2]), "r"(a[3]), "r"(b0), "r"(b1));
}

// exp(p) for p in [0,1], degree-9 Taylor (rel err < 1e-6), FMA pipe only
__device__ __forceinline__ float exp01(float p) {
    float t = 2.7557319e-6f;
    t = fmaf(t, p, 2.4801587e-5f);
    t = fmaf(t, p, 1.9841270e-4f);
    t = fmaf(t, p, 1.3888889e-3f);
    t = fmaf(t, p, 8.3333333e-3f);
    t = fmaf(t, p, 4.1666667e-2f);
    t = fmaf(t, p, 1.6666667e-1f);
    t = fmaf(t, p, 0.5f);
    t = fmaf(t, p, 1.0f);
    t = fmaf(t, p, 1.0f);
    return t;
}

// ================= split kernels =================
__global__ void splitX(const float* __restrict__ X, __nv_bfloat16* __restrict__ hi,
                       __nv_bfloat16* __restrict__ lo) {
    int i = blockIdx.x * 256 + threadIdx.x;
    float v = X[i];
    __nv_bfloat16 h = __float2bfloat16(v);
    hi[i] = h;
    lo[i] = __float2bfloat16(v - __bfloat162float(h));
}

// W[k][n] -> WT hi/lo [n][k]
__global__ void splitWT(const float* __restrict__ W, __nv_bfloat16* __restrict__ hi,
                        __nv_bfloat16* __restrict__ lo) {
    __shared__ float t[32][33];
    int bx = blockIdx.x * 32, by = blockIdx.y * 32;
    int tx = threadIdx.x & 31, ty = threadIdx.x >> 5;
#pragma unroll
    for (int i = 0; i < 32; i += 8)
        t[ty + i][tx] = W[(size_t)(by + ty + i) * 1024 + bx + tx];
    __syncthreads();
#pragma unroll
    for (int i = 0; i < 32; i += 8) {
        float v = t[tx][ty + i];
        __nv_bfloat16 h = __float2bfloat16(v);
        size_t o = (size_t)(bx + ty + i) * 1024 + by + tx;
        hi[o] = h;
        lo[o] = __float2bfloat16(v - __bfloat162float(h));
    }
}

// rope + split q,k -> bf16 hi/lo
__global__ void rope_split(const float* __restrict__ q, const float* __restrict__ k,
                           const float* __restrict__ fc, const float* __restrict__ fs,
                           __nv_bfloat16* __restrict__ qh, __nv_bfloat16* __restrict__ ql,
                           __nv_bfloat16* __restrict__ kh, __nv_bfloat16* __restrict__ kl) {
    int idx = blockIdx.x * blockDim.x + threadIdx.x;   // B*S*H*32
    int i = idx & 31;
    int h = (idx >> 5) & 15;
    int s = (idx >> 9) & (S_ - 1);
    int b = idx >> 20;
    float c  = fc[s * 32 + i];
    float sn = fs[s * 32 + i];
    size_t base = ((size_t)(b * S_ + s)) * D_ + h * DK + 2 * i;
    float a0 = q[base], a1 = q[base + 1];
    float r0 = a0 * c - a1 * sn, r1 = a0 * sn + a1 * c;
    __nv_bfloat16 h0 = __float2bfloat16(r0), h1 = __float2bfloat16(r1);
    qh[base] = h0; qh[base + 1] = h1;
    ql[base]     = __float2bfloat16(r0 - __bfloat162float(h0));
    ql[base + 1] = __float2bfloat16(r1 - __bfloat162float(h1));
    a0 = k[base]; a1 = k[base + 1];
    r0 = a0 * c - a1 * sn; r1 = a0 * sn + a1 * c;
    h0 = __float2bfloat16(r0); h1 = __float2bfloat16(r1);
    kh[base] = h0; kh[base + 1] = h1;
    kl[base]     = __float2bfloat16(r0 - __bfloat162float(h0));
    kl[base + 1] = __float2bfloat16(r1 - __bfloat162float(h1));
}

// V [b][s][h][dk] fp32 -> V^T split [b*h][dk][s] bf16 hi/lo
__global__ void vtrans_split(const float* __restrict__ v,
                             __nv_bfloat16* __restrict__ vth, __nv_bfloat16* __restrict__ vtl) {
    __shared__ float t[32][33];
    int s0 = blockIdx.x * 32, d0 = blockIdx.y * 32;
    int bh = blockIdx.z, b = bh >> 4, h = bh & 15;
    int tx = threadIdx.x & 31, ty = threadIdx.x >> 5;
#pragma unroll
    for (int i = 0; i < 32; i += 8)
        t[ty + i][tx] = v[((size_t)(b * S_ + s0 + ty + i)) * D_ + h * DK + d0 + tx];
    __syncthreads();
#pragma unroll
    for (int i = 0; i < 32; i += 8) {
        float val = t[tx][ty + i];
        __nv_bfloat16 hh = __float2bfloat16(val);
        size_t o = ((size_t)bh * DK + d0 + ty + i) * S_ + s0 + tx;
        vth[o] = hh;
        vtl[o] = __float2bfloat16(val - __bfloat162float(hh));
    }
}

// ================= projection GEMM (unchanged from R4) =================
#define SA    40
#define TILEB (128 * SA * 2)
#define BUFB  (4 * TILEB)
#define GSMEM (2 * BUFB)

__global__ __launch_bounds__(256, 1) void gemm_mma(const __nv_bfloat16* __restrict__ Ahi,
                                                   const __nv_bfloat16* __restrict__ Alo,
                                                   const __nv_bfloat16* __restrict__ Bhi,
                                                   const __nv_bfloat16* __restrict__ Blo,
                                                   float* __restrict__ C) {
    extern __shared__ char smc[];
    const int tid = threadIdx.x, lane = tid & 31, wid = tid >> 5;
    const int wm = wid & 3, wn = wid >> 2;
    const int grp = lane >> 2, qid = lane & 3;
    const int m0 = blockIdx.y * 128, n0 = blockIdx.x * 128;
    const unsigned sb = smem_u32(smc);

    const __nv_bfloat16* srcs[4] = {Ahi, Alo, Bhi, Blo};
    const int r0s[4] = {m0, m0, n0, n0};

    float acc[2][8][4];
#pragma unroll
    for (int mt = 0; mt < 2; mt++)
#pragma unroll
        for (int nt = 0; nt < 8; nt++)
#pragma unroll
            for (int e = 0; e < 4; e++) acc[mt][nt][e] = 0.f;

    {
#pragma unroll
        for (int t = 0; t < 4; t++)
#pragma unroll
            for (int u = 0; u < 2; u++) {
                int idx = tid * 2 + u;
                int row = idx >> 2, seg = idx & 3;
                cp16(sb + t * TILEB + row * 80 + seg * 16,
                     srcs[t] + (size_t)(r0s[t] + row) * 1024 + seg * 8);
            }
        cp_commit();
    }

    for (int ch = 0; ch < 32; ch++) {
        const int buf = ch & 1;
        if (ch < 31) {
            const int k0 = (ch + 1) * 32, nbuf = (ch + 1) & 1;
#pragma unroll
            for (int t = 0; t < 4; t++)
#pragma unroll
                for (int u = 0; u < 2; u++) {
                    int idx = tid * 2 + u;
                    int row = idx >> 2, seg = idx & 3;
                    cp16(sb + nbuf * BUFB + t * TILEB + row * 80 + seg * 16,
                         srcs[t] + (size_t)(r0s[t] + row) * 1024 + k0 + seg * 8);
                }
            cp_commit();
            cp_wait<1>();
        } else {
            cp_wait<0>();
        }
        __syncthreads();

        const __nv_bfloat16* Ah = (const __nv_bfloat16*)(smc + buf * BUFB);
        const __nv_bfloat16* Al = Ah + 128 * SA;
        const __nv_bfloat16* Bh = Ah + 2 * 128 * SA;
        const __nv_bfloat16* Bl = Ah + 3 * 128 * SA;

#pragma unroll
        for (int kk = 0; kk < 32; kk += 16) {
            unsigned afh[2][4], afl[2][4];
#pragma unroll
            for (int mt = 0; mt < 2; mt++) {
                int r = wm * 32 + mt * 16 + grp;
                afh[mt][0] = *(const unsigned*)&Ah[r * SA + kk + qid * 2];
                afh[mt][1] = *(const unsigned*)&Ah[(r + 8) * SA + kk + qid * 2];
                afh[mt][2] = *(const unsigned*)&Ah[r * SA + kk + 8 + qid * 2];
                afh[mt][3] = *(const unsigned*)&Ah[(r + 8) * SA + kk + 8 + qid * 2];
                afl[mt][0] = *(const unsigned*)&Al[r * SA + kk + qid * 2];
                afl[mt][1] = *(const unsigned*)&Al[(r + 8) * SA + kk + qid * 2];
                afl[mt][2] = *(const unsigned*)&Al[r * SA + kk + 8 + qid * 2];
                afl[mt][3] = *(const unsigned*)&Al[(r + 8) * SA + kk + 8 + qid * 2];
            }
#pragma unroll
            for (int nt = 0; nt < 8; nt++) {
                int c = wn * 64 + nt * 8 + grp;
                unsigned bh0 = *(const unsigned*)&Bh[c * SA + kk + qid * 2];
                unsigned bh1 = *(const unsigned*)&Bh[c * SA + kk + 8 + qid * 2];
                unsigned bl0 = *(const unsigned*)&Bl[c * SA + kk + qid * 2];
                unsigned bl1 = *(const unsigned*)&Bl[c * SA + kk + 8 + qid * 2];
#pragma unroll
                for (int mt = 0; mt < 2; mt++) {
                    mma16816(acc[mt][nt], afh[mt], bh0, bh1);
                    mma16816(acc[mt][nt], afh[mt], bl0, bl1);
                    mma16816(acc[mt][nt], afl[mt], bh0, bh1);
                }
            }
        }
        __syncthreads();
    }

#pragma unroll
    for (int mt = 0; mt < 2; mt++) {
        int r = m0 + wm * 32 + mt * 16 + grp;
#pragma unroll
        for (int nt = 0; nt < 8; nt++) {
            int c = n0 + wn * 64 + nt * 8 + qid * 2;
            *(float2*)&C[(size_t)r * 1024 + c]       = make_float2(acc[mt][nt][0], acc[mt][nt][1]);
            *(float2*)&C[(size_t)(r + 8) * 1024 + c] = make_float2(acc[mt][nt][2], acc[mt][nt][3]);
        }
    }
}

// ================= pass 1: u = exp(QK^T/8), z = sum u =================
// smem layout (bf16 stride 72/row):
//  Qh @0, Ql @18432, K buf0(h,l) @36864/@55296, K buf1 @73728/@92160, zbuf @110592
#define P1S   72
#define P1ROW (P1S * 2)       // 144 B
#define P1T   (128 * P1ROW)   // 18432 B
#define P1SMEM (6 * P1T + 1024)

__global__ __launch_bounds__(256, 1) void pass1_mma(const __nv_bfloat16* __restrict__ qh,
                                                    const __nv_bfloat16* __restrict__ ql,
                                                    const __nv_bfloat16* __restrict__ kh,
                                                    const __nv_bfloat16* __restrict__ kl) {
    extern __shared__ char smc[];
    const unsigned sb = smem_u32(smc);
    const int tid = threadIdx.x, lane = tid & 31, wid = tid >> 5;
    const int wm = wid & 3, wn = wid >> 2;
    const int grp = lane >> 2, qid = lane & 3;
    const int bh = blockIdx.y, b = bh >> 4, h = bh & 15;
    const int q0 = blockIdx.x * 128;
    float* zbuf = (float*)(smc + 6 * P1T);

    // load Q tiles (hi/lo) + K tile 0 in one group
    {
        const __nv_bfloat16* qsrc[2] = {qh, ql};
#pragma unroll
        for (int t = 0; t < 2; t++)
#pragma unroll
            for (int u = 0; u < 4; u++) {
                int idx = tid * 4 + u;                 // 0..1023
                int row = idx >> 3, ch = idx & 7;
                cp16(sb + t * P1T + row * P1ROW + ch * 16,
                     qsrc[t] + ((size_t)(b * S_ + q0 + row)) * D_ + h * DK + ch * 8);
            }
        const __nv_bfloat16* ksrc[2] = {kh, kl};
#pragma unroll
        for (int t = 0; t < 2; t++)
#pragma unroll
            for (int u = 0; u < 4; u++) {
                int idx = tid * 4 + u;
                int row = idx >> 3, ch = idx & 7;
                cp16(sb + (2 + t) * P1T + row * P1ROW + ch * 16,
                     ksrc[t] + ((size_t)(b * S_ + row)) * D_ + h * DK + ch * 8);
            }
        cp_commit();
    }

    // wait for Q (and K0), extract Q fragments to registers
    cp_wait<0>();
    __syncthreads();
    unsigned qfh[2][4][4], qfl[2][4][4];
    {
        const __nv_bfloat16* Qh = (const __nv_bfloat16*)smc;
        const __nv_bfloat16* Ql = Qh + 128 * P1S;
#pragma unroll
        for (int mt = 0; mt < 2; mt++) {
            int r = wm * 32 + mt * 16 + grp;
#pragma unroll
            for (int kk = 0; kk < 4; kk++) {
                int c0 = kk * 16 + qid * 2;
                qfh[mt][kk][0] = *(const unsigned*)&Qh[r * P1S + c0];
                qfh[mt][kk][1] = *(const unsigned*)&Qh[(r + 8) * P1S + c0];
                qfh[mt][kk][2] = *(const unsigned*)&Qh[r * P1S + c0 + 8];
                qfh[mt][kk][3] = *(const unsigned*)&Qh[(r + 8) * P1S + c0 + 8];
                qfl[mt][kk][0] = *(const unsigned*)&Ql[r * P1S + c0];
                qfl[mt][kk][1] = *(const unsigned*)&Ql[(r + 8) * P1S + c0];
                qfl[mt][kk][2] = *(const unsigned*)&Ql[r * P1S + c0 + 8];
                qfl[mt][kk][3] = *(const unsigned*)&Ql[(r + 8) * P1S + c0 + 8];
            }
        }
    }

    float zacc[2][2] = {{0.f, 0.f}, {0.f, 0.f}};

    for (int kt = 0; kt < 16; kt++) {
        const int buf = kt & 1;
        if (kt < 15) {
            const int nbuf = (kt + 1) & 1;
            const __nv_bfloat16* ksrc[2] = {kh, kl};
#pragma unroll
            for (int t = 0; t < 2; t++)
#pragma unroll
                for (int u = 0; u < 4; u++) {
                    int idx = tid * 4 + u;
                    int row = idx >> 3, ch = idx & 7;
                    cp16(sb + (2 + 2 * nbuf + t) * P1T + row * P1ROW + ch * 16,
                         ksrc[t] + ((size_t)(b * S_ + (kt + 1) * 128 + row)) * D_ + h * DK + ch * 8);
                }
            cp_commit();
            cp_wait<1>();
        } else {
            cp_wait<0>();
        }
        __syncthreads();

        const __nv_bfloat16* Kh = (const __nv_bfloat16*)(smc + (2 + 2 * buf) * P1T);
        const __nv_bfloat16* Kl = Kh + 128 * P1S;

        float acc[2][8][4];
#pragma unroll
        for (int mt = 0; mt < 2; mt++)
#pragma unroll
            for (int nt = 0; nt < 8; nt++)
#pragma unroll
                for (int e = 0; e < 4; e++) acc[mt][nt][e] = 0.f;

#pragma unroll
        for (int kk = 0; kk < 4; kk++) {
#pragma unroll
            for (int nt = 0; nt < 8; nt++) {
                int c = wn * 64 + nt * 8 + grp;
                int c0 = kk * 16 + qid * 2;
                unsigned bh0 = *(const unsigned*)&Kh[c * P1S + c0];
                unsigned bh1 = *(const unsigned*)&Kh[c * P1S + c0 + 8];
                unsigned bl0 = *(const unsigned*)&Kl[c * P1S + c0];
                unsigned bl1 = *(const unsigned*)&Kl[c * P1S + c0 + 8];
#pragma unroll
                for (int mt = 0; mt < 2; mt++) {
                    mma16816(acc[mt][nt], qfh[mt][kk], bh0, bh1);
                    mma16816(acc[mt][nt], qfh[mt][kk], bl0, bl1);
                    mma16816(acc[mt][nt], qfl[mt][kk], bh0, bh1);
                }
            }
        }

        // epilogue: u = exp(s/8) -> gmem, z += u
#pragma unroll
        for (int mt = 0; mt < 2; mt++) {
            int r = q0 + wm * 32 + mt * 16 + grp;
#pragma unroll
            for (int nt = 0; nt < 8; nt++) {
                int c = kt * 128 + wn * 64 + nt * 8 + qid * 2;
                float u0 = __expf(acc[mt][nt][0] * 0.125f);
                float u1 = __expf(acc[mt][nt][1] * 0.125f);
                float u2 = __expf(acc[mt][nt][2] * 0.125f);
                float u3 = __expf(acc[mt][nt][3] * 0.125f);
                *(float2*)&g_scores[((size_t)bh * S_ + r) * S_ + c]     = make_float2(u0, u1);
                *(float2*)&g_scores[((size_t)bh * S_ + r + 8) * S_ + c] = make_float2(u2, u3);
                zacc[mt][0] += u0 + u1;
                zacc[mt][1] += u2 + u3;
            }
        }
        __syncthreads();
    }

    // reduce z over qid lanes, then over wn
#pragma unroll
    for (int mt = 0; mt < 2; mt++)
#pragma unroll
        for (int hf = 0; hf < 2; hf++) {
            float z = zacc[mt][hf];
            z += __shfl_xor_sync(0xffffffffu, z, 1);
            z += __shfl_xor_sync(0xffffffffu, z, 2);
            if (qid == 0) zbuf[wn * 128 + wm * 32 + mt * 16 + hf * 8 + grp] = z;
        }
    __syncthreads();
    if (tid < 128) g_z[bh * S_ + q0 + tid] = zbuf[tid] + zbuf[128 + tid];
}

// ================= pass 2: t = exp(u/z); out = t @ V / sum t =================
// smem (bf16 stride 136): Th @0, Tl @34816, Vh @69632, Vl @87040, tsums @104448
#define P2S   136
#define P2ROW (P2S * 2)       // 272 B
#define P2TT  (128 * P2ROW)   // 34816 B
#define P2VT  (64 * P2ROW)    // 17408 B
#define P2SMEM (2 * P2TT + 2 * P2VT + 1024)

__global__ __launch_bounds__(256, 1) void pass2_mma(const __nv_bfloat16* __restrict__ vth,
                                                    const __nv_bfloat16* __restrict__ vtl,
                                                    float* __restrict__ attn) {
    extern __shared__ char smc[];
    const unsigned sb = smem_u32(smc);
    const int tid = threadIdx.x, lane = tid & 31, wid = tid >> 5;
    const int wm = wid & 3, wn = wid >> 2;
    const int grp = lane >> 2, qid = lane & 3;
    const int bh = blockIdx.y, b = bh >> 4, h = bh & 15;
    const int q0 = blockIdx.x * 128;
    const int ty = tid >> 4, tx = tid & 15;
    float* tsums = (float*)(smc + 2 * P2TT + 2 * P2VT);
    __nv_bfloat16* Th = (__nv_bfloat16*)smc;
    __nv_bfloat16* Tl = Th + 128 * P2S;
    const __nv_bfloat16* Vh = (const __nv_bfloat16*)(smc + 2 * P2TT);
    const __nv_bfloat16* Vl = Vh + 64 * P2S;

    float iz[8], tsum[8];
#pragma unroll
    for (int i = 0; i < 8; i++) {
        iz[i] = 1.0f / g_z[bh * S_ + q0 + ty * 8 + i];
        tsum[i] = 0.f;
    }

    float acc[2][4][4];
#pragma unroll
    for (int mt = 0; mt < 2; mt++)
#pragma unroll
        for (int nt = 0; nt < 4; nt++)
#pragma unroll
            for (int e = 0; e < 4; e++) acc[mt][nt][e] = 0.f;

    for (int kt = 0; kt < 16; kt++) {
        const int k0 = kt * 128;
        // async load V^T tiles [64 d][128 k]
        {
            const __nv_bfloat16* vsrc[2] = {vth, vtl};
#pragma unroll
            for (int t = 0; t < 2; t++)
#pragma unroll
                for (int u = 0; u < 4; u++) {
                    int idx = tid * 4 + u;             // 0..1023
                    int row = idx >> 4, ch = idx & 15;
                    cp16(sb + 2 * P2TT + t * P2VT + row * P2ROW + ch * 16,
                         vsrc[t] + ((size_t)bh * DK + row) * S_ + k0 + ch * 8);
                }
            cp_commit();
        }
        // compute t tile, store split to smem
#pragma unroll
        for (int i = 0; i < 8; i++) {
            int r = ty * 8 + i;
#pragma unroll
            for (int hf = 0; hf < 2; hf++) {
                int c = hf * 64 + tx * 4;
                float4 u4 = *(const float4*)&g_scores[((size_t)bh * S_ + q0 + r) * S_ + k0 + c];
                float t0 = exp01(u4.x * iz[i]);
                float t1 = exp01(u4.y * iz[i]);
                float t2 = exp01(u4.z * iz[i]);
                float t3 = exp01(u4.w * iz[i]);
                tsum[i] += (t0 + t1) + (t2 + t3);
                __nv_bfloat16 h0 = __float2bfloat16(t0), h1 = __float2bfloat16(t1);
                __nv_bfloat16 h2 = __float2bfloat16(t2), h3 = __float2bfloat16(t3);
                __nv_bfloat162 hi01, hi23, lo01, lo23;
                hi01.x = h0; hi01.y = h1; hi23.x = h2; hi23.y = h3;
                lo01.x = __float2bfloat16(t0 - __bfloat162float(h0));
                lo01.y = __float2bfloat16(t1 - __bfloat162float(h1));
                lo23.x = __float2bfloat16(t2 - __bfloat162float(h2));
                lo23.y = __float2bfloat16(t3 - __bfloat162float(h3));
                *(__nv_bfloat162*)&Th[r * P2S + c]     = hi01;
                *(__nv_bfloat162*)&Th[r * P2S + c + 2] = hi23;
                *(__nv_bfloat162*)&Tl[r * P2S + c]     = lo01;
                *(__nv_bfloat162*)&Tl[r * P2S + c + 2] = lo23;
            }
        }
        cp_wait<0>();
        __syncthreads();

        // mma: T[128 x 128] @ V^T fragments -> acc[128 x 64]
#pragma unroll
        for (int kk = 0; kk < 8; kk++) {
            unsigned afh[2][4], afl[2][4];
            int c0 = kk * 16 + qid * 2;
#pragma unroll
            for (int mt = 0; mt < 2; mt++) {
                int r = wm * 32 + mt * 16 + grp;
                afh[mt][0] = *(const unsigned*)&Th[r * P2S + c0];
                afh[mt][1] = *(const unsigned*)&Th[(r + 8) * P2S + c0];
                afh[mt][2] = *(const unsigned*)&Th[r * P2S + c0 + 8];
                afh[mt][3] = *(const unsigned*)&Th[(r + 8) * P2S + c0 + 8];
                afl[mt][0] = *(const unsigned*)&Tl[r * P2S + c0];
                afl[mt][1] = *(const unsigned*)&Tl[(r + 8) * P2S + c0];
                afl[mt][2] = *(const unsigned*)&Tl[r * P2S + c0 + 8];
                afl[mt][3] = *(const unsigned*)&Tl[(r + 8) * P2S + c0 + 8];
            }
#pragma unroll
            for (int nt = 0; nt < 4; nt++) {
                int c = wn * 32 + nt * 8 + grp;
                unsigned bh0 = *(const unsigned*)&Vh[c * P2S + c0];
                unsigned bh1 = *(const unsigned*)&Vh[c * P2S + c0 + 8];
                unsigned bl0 = *(const unsigned*)&Vl[c * P2S + c0];
                unsigned bl1 = *(const unsigned*)&Vl[c * P2S + c0 + 8];
#pragma unroll
                for (int mt = 0; mt < 2; mt++) {
                    mma16816(acc[mt][nt], afh[mt], bh0, bh1);
                    mma16816(acc[mt][nt], afh[mt], bl0, bl1);
                    mma16816(acc[mt][nt], afl[mt], bh0, bh1);
                }
            }
        }
        __syncthreads();
    }

    // reduce tsum over tx (within half-warp) and publish
#pragma unroll
    for (int i = 0; i < 8; i++) {
        float s = tsum[i];
        s += __shfl_xor_sync(0xffffffffu, s, 1);
        s += __shfl_xor_sync(0xffffffffu, s, 2);
        s += __shfl_xor_sync(0xffffffffu, s, 4);
        s += __shfl_xor_sync(0xffffffffu, s, 8);
        if (tx == 0) tsums[ty * 8 + i] = s;
    }
    __syncthreads();

    // epilogue: normalize and store
#pragma unroll
    for (int mt = 0; mt < 2; mt++) {
        int rl0 = wm * 32 + mt * 16 + grp;
        float r0 = 1.0f / tsums[rl0];
        float r1 = 1.0f / tsums[rl0 + 8];
#pragma unroll
        for (int nt = 0; nt < 4; nt++) {
            int c = h * DK + wn * 32 + nt * 8 + qid * 2;
            size_t o0 = ((size_t)(b * S_ + q0 + rl0)) * D_ + c;
            size_t o1 = ((size_t)(b * S_ + q0 + rl0 + 8)) * D_ + c;
            *(float2*)&attn[o0] = make_float2(acc[mt][nt][0] * r0, acc[mt][nt][1] * r0);
            *(float2*)&attn[o1] = make_float2(acc[mt][nt][2] * r1, acc[mt][nt][3] * r1);
        }
    }
}

// ---------------- launch ----------------
extern "C" void kernel_launch(void* const* d_in, const int* in_sizes, int n_in,
                              void* d_out, int out_size) {
    const float* x  = (const float*)d_in[0];
    const float* fc = (const float*)d_in[1];
    const float* fs = (const float*)d_in[2];
    const float* W[4] = {(const float*)d_in[3], (const float*)d_in[4],
                         (const float*)d_in[5], (const float*)d_in[6]};
    float* out = (float*)d_out;

    float *q, *k, *v, *attn;
    __nv_bfloat16 *xhi, *xlo, *ahi, *alo, *wthi, *wtlo, *qh, *ql, *kh, *kl, *vth, *vtl;
    cudaGetSymbolAddress((void**)&q, g_q);
    cudaGetSymbolAddress((void**)&k, g_k);
    cudaGetSymbolAddress((void**)&v, g_v);
    cudaGetSymbolAddress((void**)&attn, g_attn);
    cudaGetSymbolAddress((void**)&xhi, g_xhi);
    cudaGetSymbolAddress((void**)&xlo, g_xlo);
    cudaGetSymbolAddress((void**)&ahi, g_ahi);
    cudaGetSymbolAddress((void**)&alo, g_alo);
    cudaGetSymbolAddress((void**)&wthi, g_wthi);
    cudaGetSymbolAddress((void**)&wtlo, g_wtlo);
    cudaGetSymbolAddress((void**)&qh, g_qh);
    cudaGetSymbolAddress((void**)&ql, g_ql);
    cudaGetSymbolAddress((void**)&kh, g_kh);
    cudaGetSymbolAddress((void**)&kl, g_kl);
    cudaGetSymbolAddress((void**)&vth, g_vth);
    cudaGetSymbolAddress((void**)&vtl, g_vtl);

    cudaFuncSetAttribute(gemm_mma, cudaFuncAttributeMaxDynamicSharedMemorySize, GSMEM);
    cudaFuncSetAttribute(pass1_mma, cudaFuncAttributeMaxDynamicSharedMemorySize, P1SMEM);
    cudaFuncSetAttribute(pass2_mma, cudaFuncAttributeMaxDynamicSharedMemorySize, P2SMEM);

    splitX<<<(MS_ * D_) / 256, 256>>>(x, xhi, xlo);
    for (int i = 0; i < 4; i++)
        splitWT<<<dim3(32, 32), 256>>>(W[i], wthi + (size_t)i * D_ * D_,
                                       wtlo + (size_t)i * D_ * D_);

    dim3 ggrid(8, 32);
    gemm_mma<<<ggrid, 256, GSMEM>>>(xhi, xlo, wthi + 0 * (size_t)D_ * D_,
                                    wtlo + 0 * (size_t)D_ * D_, q);
    gemm_mma<<<ggrid, 256, GSMEM>>>(xhi, xlo, wthi + 1 * (size_t)D_ * D_,
                                    wtlo + 1 * (size_t)D_ * D_, k);
    gemm_mma<<<ggrid, 256, GSMEM>>>(xhi, xlo, wthi + 2 * (size_t)D_ * D_,
                                    wtlo + 2 * (size_t)D_ * D_, v);

    rope_split<<<(B_ * S_ * H_ * (DK / 2)) / 256, 256>>>(q, k, fc, fs, qh, ql, kh, kl);
    vtrans_split<<<dim3(S_ / 32, DK / 32, BH_), 256>>>(v, vth, vtl);

    pass1_mma<<<dim3(S_ / 128, BH_), 256, P1SMEM>>>(qh, ql, kh, kl);
    pass2_mma<<<dim3(S_ / 128, BH_), 256, P2SMEM>>>(vth, vtl, attn);

    splitX<<<(MS_ * D_) / 256, 256>>>(attn, ahi, alo);
    gemm_mma<<<ggrid, 256, GSMEM>>>(ahi, alo, wthi + 3 * (size_t)D_ * D_,
                                    wtlo + 3 * (size_t)D_ * D_, out);
}

// round 7
// speedup vs baseline: 2.7035x; 1.4918x over previous
#include <cuda_runtime.h>
#include <cuda_bf16.h>
#include <cuda_fp16.h>
#include <math.h>

#define B_  2
#define S_  2048
#define D_  1024
#define H_  16
#define DK  64
#define BH_ (B_*H_)
#define MS_ (B_*S_)          // 4096 rows

// ---------------- scratch (static device arrays; no cudaMalloc) ----------------
__device__ float g_q[(size_t)MS_*D_];
__device__ float g_k[(size_t)MS_*D_];
__device__ float g_v[(size_t)MS_*D_];
__device__ float g_attn[(size_t)MS_*D_];
__device__ __half g_sh[(size_t)BH_*S_*S_];      // scaled scores s/8, fp16 (256 MB)
__device__ float g_z[BH_*S_];
__device__ float g_sumv[BH_*DK];
// bf16 split buffers
__device__ __nv_bfloat16 g_xhi[(size_t)MS_*D_];
__device__ __nv_bfloat16 g_xlo[(size_t)MS_*D_];
__device__ __nv_bfloat16 g_ahi[(size_t)MS_*D_];
__device__ __nv_bfloat16 g_alo[(size_t)MS_*D_];
__device__ __nv_bfloat16 g_wthi[4][(size_t)D_*D_];   // W^T hi ([n][k])
__device__ __nv_bfloat16 g_wtlo[4][(size_t)D_*D_];
// roped q/k bf16 ([b][s][h][dk]) and transposed V bf16 ([b*h][dk][s])
__device__ __nv_bfloat16 g_qh[(size_t)MS_*D_];
__device__ __nv_bfloat16 g_kh[(size_t)MS_*D_];
__device__ __nv_bfloat16 g_vth[(size_t)BH_*DK*S_];

// ================= helpers =================
__device__ __forceinline__ unsigned smem_u32(const void* p) {
    unsigned a;
    asm("{ .reg .u64 t; cvta.to.shared.u64 t, %1; cvt.u32.u64 %0, t; }" : "=r"(a) : "l"(p));
    return a;
}
__device__ __forceinline__ void cp16(unsigned saddr, const void* gaddr) {
    asm volatile("cp.async.cg.shared.global [%0], [%1], 16;" :: "r"(saddr), "l"(gaddr));
}
__device__ __forceinline__ void cp_commit() { asm volatile("cp.async.commit_group;"); }
template <int N>
__device__ __forceinline__ void cp_wait() { asm volatile("cp.async.wait_group %0;" :: "n"(N)); }

__device__ __forceinline__ void mma16816(float* c, const unsigned* a, unsigned b0, unsigned b1) {
    asm volatile("mma.sync.aligned.m16n8k16.row.col.f32.bf16.bf16.f32 "
                 "{%0,%1,%2,%3}, {%4,%5,%6,%7}, {%8,%9}, {%0,%1,%2,%3};"
                 : "+f"(c[0]), "+f"(c[1]), "+f"(c[2]), "+f"(c[3])
                 : "r"(a[0]), "r"(a[1]), "r"(a[2]), "r"(a[3]), "r"(b0), "r"(b1));
}

// ================= split / transform kernels =================
__global__ void splitX(const float* __restrict__ X, __nv_bfloat16* __restrict__ hi,
                       __nv_bfloat16* __restrict__ lo) {
    int i = blockIdx.x * 256 + threadIdx.x;
    float v = X[i];
    __nv_bfloat16 h = __float2bfloat16(v);
    hi[i] = h;
    lo[i] = __float2bfloat16(v - __bfloat162float(h));
}

// W[k][n] -> WT hi/lo [n][k]
__global__ void splitWT(const float* __restrict__ W, __nv_bfloat16* __restrict__ hi,
                        __nv_bfloat16* __restrict__ lo) {
    __shared__ float t[32][33];
    int bx = blockIdx.x * 32, by = blockIdx.y * 32;
    int tx = threadIdx.x & 31, ty = threadIdx.x >> 5;
#pragma unroll
    for (int i = 0; i < 32; i += 8)
        t[ty + i][tx] = W[(size_t)(by + ty + i) * 1024 + bx + tx];
    __syncthreads();
#pragma unroll
    for (int i = 0; i < 32; i += 8) {
        float v = t[tx][ty + i];
        __nv_bfloat16 h = __float2bfloat16(v);
        size_t o = (size_t)(bx + ty + i) * 1024 + by + tx;
        hi[o] = h;
        lo[o] = __float2bfloat16(v - __bfloat162float(h));
    }
}

// rope then bf16 (hi only)
__global__ void rope_split(const float* __restrict__ q, const float* __restrict__ k,
                           const float* __restrict__ fc, const float* __restrict__ fs,
                           __nv_bfloat16* __restrict__ qh, __nv_bfloat16* __restrict__ kh) {
    int idx = blockIdx.x * blockDim.x + threadIdx.x;
    int i = idx & 31;
    int h = (idx >> 5) & 15;
    int s = (idx >> 9) & (S_ - 1);
    int b = idx >> 20;
    float c  = fc[s * 32 + i];
    float sn = fs[s * 32 + i];
    size_t base = ((size_t)(b * S_ + s)) * D_ + h * DK + 2 * i;
    float a0 = q[base], a1 = q[base + 1];
    qh[base]     = __float2bfloat16(a0 * c - a1 * sn);
    qh[base + 1] = __float2bfloat16(a0 * sn + a1 * c);
    a0 = k[base]; a1 = k[base + 1];
    kh[base]     = __float2bfloat16(a0 * c - a1 * sn);
    kh[base + 1] = __float2bfloat16(a0 * sn + a1 * c);
}

// V [b][s][h][dk] fp32 -> V^T [b*h][dk][s] bf16
__global__ void vtrans(const float* __restrict__ v, __nv_bfloat16* __restrict__ vth) {
    __shared__ float t[32][33];
    int s0 = blockIdx.x * 32, d0 = blockIdx.y * 32;
    int bh = blockIdx.z, b = bh >> 4, h = bh & 15;
    int tx = threadIdx.x & 31, ty = threadIdx.x >> 5;
#pragma unroll
    for (int i = 0; i < 32; i += 8)
        t[ty + i][tx] = v[((size_t)(b * S_ + s0 + ty + i)) * D_ + h * DK + d0 + tx];
    __syncthreads();
#pragma unroll
    for (int i = 0; i < 32; i += 8)
        vth[((size_t)bh * DK + d0 + ty + i) * S_ + s0 + tx] = __float2bfloat16(t[tx][ty + i]);
}

// sumv[bh][d] = sum_s v[b][s][h][d]  (exact fp32)
__global__ void sumv_kernel(const float* __restrict__ v, float* __restrict__ sumv) {
    int bh = blockIdx.x, b = bh >> 4, h = bh & 15;
    int d = threadIdx.x & 63, sc = threadIdx.x >> 6;
    float s = 0.f;
    for (int i = 0; i < 512; i++)
        s += v[((size_t)(b * S_ + sc * 512 + i)) * D_ + h * DK + d];
    __shared__ float red[256];
    red[threadIdx.x] = s;
    __syncthreads();
    if (sc == 0) sumv[bh * DK + d] = red[d] + red[64 + d] + red[128 + d] + red[192 + d];
}

// ================= 3-term projection GEMM (Wv, Wo) =================
#define SA    40
#define TILEB (128 * SA * 2)
#define BUFB  (4 * TILEB)
#define GSMEM (2 * BUFB)

__global__ __launch_bounds__(256, 1) void gemm_mma(const __nv_bfloat16* __restrict__ Ahi,
                                                   const __nv_bfloat16* __restrict__ Alo,
                                                   const __nv_bfloat16* __restrict__ Bhi,
                                                   const __nv_bfloat16* __restrict__ Blo,
                                                   float* __restrict__ C) {
    extern __shared__ char smc[];
    const int tid = threadIdx.x, lane = tid & 31, wid = tid >> 5;
    const int wm = wid & 3, wn = wid >> 2;
    const int grp = lane >> 2, qid = lane & 3;
    const int m0 = blockIdx.y * 128, n0 = blockIdx.x * 128;
    const unsigned sb = smem_u32(smc);

    const __nv_bfloat16* srcs[4] = {Ahi, Alo, Bhi, Blo};
    const int r0s[4] = {m0, m0, n0, n0};

    float acc[2][8][4];
#pragma unroll
    for (int mt = 0; mt < 2; mt++)
#pragma unroll
        for (int nt = 0; nt < 8; nt++)
#pragma unroll
            for (int e = 0; e < 4; e++) acc[mt][nt][e] = 0.f;

    {
#pragma unroll
        for (int t = 0; t < 4; t++)
#pragma unroll
            for (int u = 0; u < 2; u++) {
                int idx = tid * 2 + u;
                int row = idx >> 2, seg = idx & 3;
                cp16(sb + t * TILEB + row * 80 + seg * 16,
                     srcs[t] + (size_t)(r0s[t] + row) * 1024 + seg * 8);
            }
        cp_commit();
    }

    for (int ch = 0; ch < 32; ch++) {
        const int buf = ch & 1;
        if (ch < 31) {
            const int k0 = (ch + 1) * 32, nbuf = (ch + 1) & 1;
#pragma unroll
            for (int t = 0; t < 4; t++)
#pragma unroll
                for (int u = 0; u < 2; u++) {
                    int idx = tid * 2 + u;
                    int row = idx >> 2, seg = idx & 3;
                    cp16(sb + nbuf * BUFB + t * TILEB + row * 80 + seg * 16,
                         srcs[t] + (size_t)(r0s[t] + row) * 1024 + k0 + seg * 8);
                }
            cp_commit();
            cp_wait<1>();
        } else {
            cp_wait<0>();
        }
        __syncthreads();

        const __nv_bfloat16* Ah = (const __nv_bfloat16*)(smc + buf * BUFB);
        const __nv_bfloat16* Al = Ah + 128 * SA;
        const __nv_bfloat16* Bh = Ah + 2 * 128 * SA;
        const __nv_bfloat16* Bl = Ah + 3 * 128 * SA;

#pragma unroll
        for (int kk = 0; kk < 32; kk += 16) {
            unsigned afh[2][4], afl[2][4];
#pragma unroll
            for (int mt = 0; mt < 2; mt++) {
                int r = wm * 32 + mt * 16 + grp;
                afh[mt][0] = *(const unsigned*)&Ah[r * SA + kk + qid * 2];
                afh[mt][1] = *(const unsigned*)&Ah[(r + 8) * SA + kk + qid * 2];
                afh[mt][2] = *(const unsigned*)&Ah[r * SA + kk + 8 + qid * 2];
                afh[mt][3] = *(const unsigned*)&Ah[(r + 8) * SA + kk + 8 + qid * 2];
                afl[mt][0] = *(const unsigned*)&Al[r * SA + kk + qid * 2];
                afl[mt][1] = *(const unsigned*)&Al[(r + 8) * SA + kk + qid * 2];
                afl[mt][2] = *(const unsigned*)&Al[r * SA + kk + 8 + qid * 2];
                afl[mt][3] = *(const unsigned*)&Al[(r + 8) * SA + kk + 8 + qid * 2];
            }
#pragma unroll
            for (int nt = 0; nt < 8; nt++) {
                int c = wn * 64 + nt * 8 + grp;
                unsigned bh0 = *(const unsigned*)&Bh[c * SA + kk + qid * 2];
                unsigned bh1 = *(const unsigned*)&Bh[c * SA + kk + 8 + qid * 2];
                unsigned bl0 = *(const unsigned*)&Bl[c * SA + kk + qid * 2];
                unsigned bl1 = *(const unsigned*)&Bl[c * SA + kk + 8 + qid * 2];
#pragma unroll
                for (int mt = 0; mt < 2; mt++) {
                    mma16816(acc[mt][nt], afh[mt], bh0, bh1);
                    mma16816(acc[mt][nt], afh[mt], bl0, bl1);
                    mma16816(acc[mt][nt], afl[mt], bh0, bh1);
                }
            }
        }
        __syncthreads();
    }

#pragma unroll
    for (int mt = 0; mt < 2; mt++) {
        int r = m0 + wm * 32 + mt * 16 + grp;
#pragma unroll
        for (int nt = 0; nt < 8; nt++) {
            int c = n0 + wn * 64 + nt * 8 + qid * 2;
            *(float2*)&C[(size_t)r * 1024 + c]       = make_float2(acc[mt][nt][0], acc[mt][nt][1]);
            *(float2*)&C[(size_t)(r + 8) * 1024 + c] = make_float2(acc[mt][nt][2], acc[mt][nt][3]);
        }
    }
}

// ================= 1-term projection GEMM (Wq, Wk) =================
#define B1B (2 * TILEB)
#define G1SMEM (2 * B1B)

__global__ __launch_bounds__(256, 1) void gemm1_mma(const __nv_bfloat16* __restrict__ Ahi,
                                                    const __nv_bfloat16* __restrict__ Bhi,
                                                    float* __restrict__ C) {
    extern __shared__ char smc[];
    const int tid = threadIdx.x, lane = tid & 31, wid = tid >> 5;
    const int wm = wid & 3, wn = wid >> 2;
    const int grp = lane >> 2, qid = lane & 3;
    const int m0 = blockIdx.y * 128, n0 = blockIdx.x * 128;
    const unsigned sb = smem_u32(smc);

    const __nv_bfloat16* srcs[2] = {Ahi, Bhi};
    const int r0s[2] = {m0, n0};

    float acc[2][8][4];
#pragma unroll
    for (int mt = 0; mt < 2; mt++)
#pragma unroll
        for (int nt = 0; nt < 8; nt++)
#pragma unroll
            for (int e = 0; e < 4; e++) acc[mt][nt][e] = 0.f;

    {
#pragma unroll
        for (int t = 0; t < 2; t++)
#pragma unroll
            for (int u = 0; u < 2; u++) {
                int idx = tid * 2 + u;
                int row = idx >> 2, seg = idx & 3;
                cp16(sb + t * TILEB + row * 80 + seg * 16,
                     srcs[t] + (size_t)(r0s[t] + row) * 1024 + seg * 8);
            }
        cp_commit();
    }

    for (int ch = 0; ch < 32; ch++) {
        const int buf = ch & 1;
        if (ch < 31) {
            const int k0 = (ch + 1) * 32, nbuf = (ch + 1) & 1;
#pragma unroll
            for (int t = 0; t < 2; t++)
#pragma unroll
                for (int u = 0; u < 2; u++) {
                    int idx = tid * 2 + u;
                    int row = idx >> 2, seg = idx & 3;
                    cp16(sb + nbuf * B1B + t * TILEB + row * 80 + seg * 16,
                         srcs[t] + (size_t)(r0s[t] + row) * 1024 + k0 + seg * 8);
                }
            cp_commit();
            cp_wait<1>();
        } else {
            cp_wait<0>();
        }
        __syncthreads();

        const __nv_bfloat16* Ah = (const __nv_bfloat16*)(smc + buf * B1B);
        const __nv_bfloat16* Bh = Ah + 128 * SA;

#pragma unroll
        for (int kk = 0; kk < 32; kk += 16) {
            unsigned afh[2][4];
#pragma unroll
            for (int mt = 0; mt < 2; mt++) {
                int r = wm * 32 + mt * 16 + grp;
                afh[mt][0] = *(const unsigned*)&Ah[r * SA + kk + qid * 2];
                afh[mt][1] = *(const unsigned*)&Ah[(r + 8) * SA + kk + qid * 2];
                afh[mt][2] = *(const unsigned*)&Ah[r * SA + kk + 8 + qid * 2];
                afh[mt][3] = *(const unsigned*)&Ah[(r + 8) * SA + kk + 8 + qid * 2];
            }
#pragma unroll
            for (int nt = 0; nt < 8; nt++) {
                int c = wn * 64 + nt * 8 + grp;
                unsigned bh0 = *(const unsigned*)&Bh[c * SA + kk + qid * 2];
                unsigned bh1 = *(const unsigned*)&Bh[c * SA + kk + 8 + qid * 2];
#pragma unroll
                for (int mt = 0; mt < 2; mt++)
                    mma16816(acc[mt][nt], afh[mt], bh0, bh1);
            }
        }
        __syncthreads();
    }

#pragma unroll
    for (int mt = 0; mt < 2; mt++) {
        int r = m0 + wm * 32 + mt * 16 + grp;
#pragma unroll
        for (int nt = 0; nt < 8; nt++) {
            int c = n0 + wn * 64 + nt * 8 + qid * 2;
            *(float2*)&C[(size_t)r * 1024 + c]       = make_float2(acc[mt][nt][0], acc[mt][nt][1]);
            *(float2*)&C[(size_t)(r + 8) * 1024 + c] = make_float2(acc[mt][nt][2], acc[mt][nt][3]);
        }
    }
}

// ================= pass 1: s' = QK^T/8 -> fp16, z = sum exp(s') =================
#define P1S   72
#define P1ROW (P1S * 2)
#define P1T   (128 * P1ROW)   // 18432
#define P1SMEM (3 * P1T + 1024)

__global__ __launch_bounds__(256, 1) void pass1_mma(const __nv_bfloat16* __restrict__ qh,
                                                    const __nv_bfloat16* __restrict__ kh) {
    extern __shared__ char smc[];
    const unsigned sb = smem_u32(smc);
    const int tid = threadIdx.x, lane = tid & 31, wid = tid >> 5;
    const int wm = wid & 3, wn = wid >> 2;
    const int grp = lane >> 2, qid = lane & 3;
    const int bh = blockIdx.y, b = bh >> 4, h = bh & 15;
    const int q0 = blockIdx.x * 128;
    float* zbuf = (float*)(smc + 3 * P1T);

    // load Q + K0 (each tile: 128 rows x 64 bf16 = 128 B/row)
    {
#pragma unroll
        for (int u = 0; u < 4; u++) {
            int idx = tid * 4 + u;
            int row = idx >> 3, ch = idx & 7;
            cp16(sb + row * P1ROW + ch * 16,
                 qh + ((size_t)(b * S_ + q0 + row)) * D_ + h * DK + ch * 8);
        }
#pragma unroll
        for (int u = 0; u < 4; u++) {
            int idx = tid * 4 + u;
            int row = idx >> 3, ch = idx & 7;
            cp16(sb + P1T + row * P1ROW + ch * 16,
                 kh + ((size_t)(b * S_ + row)) * D_ + h * DK + ch * 8);
        }
        cp_commit();
    }
    cp_wait<0>();
    __syncthreads();

    unsigned qf[2][4][4];
    {
        const __nv_bfloat16* Qh = (const __nv_bfloat16*)smc;
#pragma unroll
        for (int mt = 0; mt < 2; mt++) {
            int r = wm * 32 + mt * 16 + grp;
#pragma unroll
            for (int kk = 0; kk < 4; kk++) {
                int c0 = kk * 16 + qid * 2;
                qf[mt][kk][0] = *(const unsigned*)&Qh[r * P1S + c0];
                qf[mt][kk][1] = *(const unsigned*)&Qh[(r + 8) * P1S + c0];
                qf[mt][kk][2] = *(const unsigned*)&Qh[r * P1S + c0 + 8];
                qf[mt][kk][3] = *(const unsigned*)&Qh[(r + 8) * P1S + c0 + 8];
            }
        }
    }

    float zacc[2][2] = {{0.f, 0.f}, {0.f, 0.f}};

    for (int kt = 0; kt < 16; kt++) {
        const int buf = kt & 1;
        if (kt < 15) {
            const int nbuf = (kt + 1) & 1;
#pragma unroll
            for (int u = 0; u < 4; u++) {
                int idx = tid * 4 + u;
                int row = idx >> 3, ch = idx & 7;
                cp16(sb + (1 + nbuf) * P1T + row * P1ROW + ch * 16,
                     kh + ((size_t)(b * S_ + (kt + 1) * 128 + row)) * D_ + h * DK + ch * 8);
            }
            cp_commit();
            cp_wait<1>();
        } else {
            cp_wait<0>();
        }
        __syncthreads();

        const __nv_bfloat16* Kh = (const __nv_bfloat16*)(smc + (1 + buf) * P1T);

        float acc[2][8][4];
#pragma unroll
        for (int mt = 0; mt < 2; mt++)
#pragma unroll
            for (int nt = 0; nt < 8; nt++)
#pragma unroll
                for (int e = 0; e < 4; e++) acc[mt][nt][e] = 0.f;

#pragma unroll
        for (int kk = 0; kk < 4; kk++) {
#pragma unroll
            for (int nt = 0; nt < 8; nt++) {
                int c = wn * 64 + nt * 8 + grp;
                int c0 = kk * 16 + qid * 2;
                unsigned bh0 = *(const unsigned*)&Kh[c * P1S + c0];
                unsigned bh1 = *(const unsigned*)&Kh[c * P1S + c0 + 8];
#pragma unroll
                for (int mt = 0; mt < 2; mt++)
                    mma16816(acc[mt][nt], qf[mt][kk], bh0, bh1);
            }
        }

        // epilogue: s' = s/8 -> fp16, z += exp(s')
#pragma unroll
        for (int mt = 0; mt < 2; mt++) {
            int r = q0 + wm * 32 + mt * 16 + grp;
#pragma unroll
            for (int nt = 0; nt < 8; nt++) {
                int c = kt * 128 + wn * 64 + nt * 8 + qid * 2;
                float s0 = acc[mt][nt][0] * 0.125f, s1 = acc[mt][nt][1] * 0.125f;
                float s2 = acc[mt][nt][2] * 0.125f, s3 = acc[mt][nt][3] * 0.125f;
                *(__half2*)&g_sh[((size_t)bh * S_ + r) * S_ + c]     = __floats2half2_rn(s0, s1);
                *(__half2*)&g_sh[((size_t)bh * S_ + r + 8) * S_ + c] = __floats2half2_rn(s2, s3);
                zacc[mt][0] += __expf(s0) + __expf(s1);
                zacc[mt][1] += __expf(s2) + __expf(s3);
            }
        }
        __syncthreads();
    }

#pragma unroll
    for (int mt = 0; mt < 2; mt++)
#pragma unroll
        for (int hf = 0; hf < 2; hf++) {
            float z = zacc[mt][hf];
            z += __shfl_xor_sync(0xffffffffu, z, 1);
            z += __shfl_xor_sync(0xffffffffu, z, 2);
            if (qid == 0) zbuf[wn * 128 + wm * 32 + mt * 16 + hf * 8 + grp] = z;
        }
    __syncthreads();
    if (tid < 128) g_z[bh * S_ + q0 + tid] = zbuf[tid] + zbuf[128 + tid];
}

// ================= pass 2: p' = expm1(exp(s')/z); out = (sumv + p'V)/(2048+sum p') ===
#define P2S   136
#define P2ROW (P2S * 2)
#define P2TT  (128 * P2ROW)   // 34816
#define P2VT  (64 * P2ROW)    // 17408
#define P2SMEM (P2TT + P2VT + 1024)

__global__ __launch_bounds__(256, 1) void pass2_mma(const __nv_bfloat16* __restrict__ vth,
                                                    const float* __restrict__ sumv,
                                                    float* __restrict__ attn) {
    extern __shared__ char smc[];
    const unsigned sb = smem_u32(smc);
    const int tid = threadIdx.x, lane = tid & 31, wid = tid >> 5;
    const int wm = wid & 3, wn = wid >> 2;
    const int grp = lane >> 2, qid = lane & 3;
    const int bh = blockIdx.y, b = bh >> 4, h = bh & 15;
    const int q0 = blockIdx.x * 128;
    const int ty = tid >> 4, tx = tid & 15;
    float* tsums = (float*)(smc + P2TT + P2VT);
    __nv_bfloat16* Th = (__nv_bfloat16*)smc;
    const __nv_bfloat16* Vh = (const __nv_bfloat16*)(smc + P2TT);

    float iz[8], tsum[8];
#pragma unroll
    for (int i = 0; i < 8; i++) {
        iz[i] = 1.0f / g_z[bh * S_ + q0 + ty * 8 + i];
        tsum[i] = 0.f;
    }

    float acc[2][4][4];
#pragma unroll
    for (int mt = 0; mt < 2; mt++)
#pragma unroll
        for (int nt = 0; nt < 4; nt++)
#pragma unroll
            for (int e = 0; e < 4; e++) acc[mt][nt][e] = 0.f;

    for (int kt = 0; kt < 16; kt++) {
        const int k0 = kt * 128;
        // async load V^T tile [64 d][128 k] : 256 B of data per row
        {
#pragma unroll
            for (int u = 0; u < 4; u++) {
                int idx = tid * 4 + u;                 // 0..1023
                int row = idx >> 4, ch = idx & 15;
                cp16(sb + P2TT + row * P2ROW + ch * 16,
                     vth + ((size_t)bh * DK + row) * S_ + k0 + ch * 8);
            }
            cp_commit();
        }
        // compute p' tile from fp16 scores
#pragma unroll
        for (int i = 0; i < 8; i++) {
            int r = ty * 8 + i;
#pragma unroll
            for (int hf = 0; hf < 2; hf++) {
                int c = hf * 64 + tx * 4;
                struct alignas(8) H4 { __half2 a, b; };
                H4 s4 = *(const H4*)&g_sh[((size_t)bh * S_ + q0 + r) * S_ + k0 + c];
                float2 f01 = __half22float2(s4.a);
                float2 f23 = __half22float2(s4.b);
                float p0 = __expf(f01.x) * iz[i];
                float p1 = __expf(f01.y) * iz[i];
                float p2 = __expf(f23.x) * iz[i];
                float p3 = __expf(f23.y) * iz[i];
                float t0 = fmaf(0.5f * p0, p0, p0);   // expm1(p), p <= ~0.006
                float t1 = fmaf(0.5f * p1, p1, p1);
                float t2 = fmaf(0.5f * p2, p2, p2);
                float t3 = fmaf(0.5f * p3, p3, p3);
                tsum[i] += (t0 + t1) + (t2 + t3);
                __nv_bfloat162 h01, h23;
                h01.x = __float2bfloat16(t0); h01.y = __float2bfloat16(t1);
                h23.x = __float2bfloat16(t2); h23.y = __float2bfloat16(t3);
                *(__nv_bfloat162*)&Th[r * P2S + c]     = h01;
                *(__nv_bfloat162*)&Th[r * P2S + c + 2] = h23;
            }
        }
        cp_wait<0>();
        __syncthreads();

        // mma: T[128x128] @ V^T -> acc[128x64]
#pragma unroll
        for (int kk = 0; kk < 8; kk++) {
            unsigned af[2][4];
            int c0 = kk * 16 + qid * 2;
#pragma unroll
            for (int mt = 0; mt < 2; mt++) {
                int r = wm * 32 + mt * 16 + grp;
                af[mt][0] = *(const unsigned*)&Th[r * P2S + c0];
                af[mt][1] = *(const unsigned*)&Th[(r + 8) * P2S + c0];
                af[mt][2] = *(const unsigned*)&Th[r * P2S + c0 + 8];
                af[mt][3] = *(const unsigned*)&Th[(r + 8) * P2S + c0 + 8];
            }
#pragma unroll
            for (int nt = 0; nt < 4; nt++) {
                int c = wn * 32 + nt * 8 + grp;
                unsigned bh0 = *(const unsigned*)&Vh[c * P2S + c0];
                unsigned bh1 = *(const unsigned*)&Vh[c * P2S + c0 + 8];
#pragma unroll
                for (int mt = 0; mt < 2; mt++)
                    mma16816(acc[mt][nt], af[mt], bh0, bh1);
            }
        }
        __syncthreads();
    }

    // reduce p'-sums across the 16 tx lanes
#pragma unroll
    for (int i = 0; i < 8; i++) {
        float s = tsum[i];
        s += __shfl_xor_sync(0xffffffffu, s, 1);
        s += __shfl_xor_sync(0xffffffffu, s, 2);
        s += __shfl_xor_sync(0xffffffffu, s, 4);
        s += __shfl_xor_sync(0xffffffffu, s, 8);
        if (tx == 0) tsums[ty * 8 + i] = s;
    }
    __syncthreads();

    // epilogue: out = (sumv + acc) / (2048 + sum p')
#pragma unroll
    for (int mt = 0; mt < 2; mt++) {
        int rl0 = wm * 32 + mt * 16 + grp;
        float r0 = 1.0f / (2048.0f + tsums[rl0]);
        float r1 = 1.0f / (2048.0f + tsums[rl0 + 8]);
#pragma unroll
        for (int nt = 0; nt < 4; nt++) {
            int dcol = wn * 32 + nt * 8 + qid * 2;
            float sv0 = sumv[bh * DK + dcol];
            float sv1 = sumv[bh * DK + dcol + 1];
            int c = h * DK + dcol;
            size_t o0 = ((size_t)(b * S_ + q0 + rl0)) * D_ + c;
            size_t o1 = ((size_t)(b * S_ + q0 + rl0 + 8)) * D_ + c;
            *(float2*)&attn[o0] = make_float2((sv0 + acc[mt][nt][0]) * r0,
                                             (sv1 + acc[mt][nt][1]) * r0);
            *(float2*)&attn[o1] = make_float2((sv0 + acc[mt][nt][2]) * r1,
                                             (sv1 + acc[mt][nt][3]) * r1);
        }
    }
}

// ---------------- launch ----------------
extern "C" void kernel_launch(void* const* d_in, const int* in_sizes, int n_in,
                              void* d_out, int out_size) {
    const float* x  = (const float*)d_in[0];
    const float* fc = (const float*)d_in[1];
    const float* fs = (const float*)d_in[2];
    const float* W[4] = {(const float*)d_in[3], (const float*)d_in[4],
                         (const float*)d_in[5], (const float*)d_in[6]};
    float* out = (float*)d_out;

    float *q, *k, *v, *attn, *sumvp;
    __nv_bfloat16 *xhi, *xlo, *ahi, *alo, *wthi, *wtlo, *qh, *kh, *vth;
    cudaGetSymbolAddress((void**)&q, g_q);
    cudaGetSymbolAddress((void**)&k, g_k);
    cudaGetSymbolAddress((void**)&v, g_v);
    cudaGetSymbolAddress((void**)&attn, g_attn);
    cudaGetSymbolAddress((void**)&sumvp, g_sumv);
    cudaGetSymbolAddress((void**)&xhi, g_xhi);
    cudaGetSymbolAddress((void**)&xlo, g_xlo);
    cudaGetSymbolAddress((void**)&ahi, g_ahi);
    cudaGetSymbolAddress((void**)&alo, g_alo);
    cudaGetSymbolAddress((void**)&wthi, g_wthi);
    cudaGetSymbolAddress((void**)&wtlo, g_wtlo);
    cudaGetSymbolAddress((void**)&qh, g_qh);
    cudaGetSymbolAddress((void**)&kh, g_kh);
    cudaGetSymbolAddress((void**)&vth, g_vth);

    cudaFuncSetAttribute(gemm_mma, cudaFuncAttributeMaxDynamicSharedMemorySize, GSMEM);
    cudaFuncSetAttribute(gemm1_mma, cudaFuncAttributeMaxDynamicSharedMemorySize, G1SMEM);
    cudaFuncSetAttribute(pass1_mma, cudaFuncAttributeMaxDynamicSharedMemorySize, P1SMEM);
    cudaFuncSetAttribute(pass2_mma, cudaFuncAttributeMaxDynamicSharedMemorySize, P2SMEM);

    splitX<<<(MS_ * D_) / 256, 256>>>(x, xhi, xlo);
    for (int i = 0; i < 4; i++)
        splitWT<<<dim3(32, 32), 256>>>(W[i], wthi + (size_t)i * D_ * D_,
                                       wtlo + (size_t)i * D_ * D_);

    dim3 ggrid(8, 32);
    gemm1_mma<<<ggrid, 256, G1SMEM>>>(xhi, wthi + 0 * (size_t)D_ * D_, q);
    gemm1_mma<<<ggrid, 256, G1SMEM>>>(xhi, wthi + 1 * (size_t)D_ * D_, k);
    gemm_mma<<<ggrid, 256, GSMEM>>>(xhi, xlo, wthi + 2 * (size_t)D_ * D_,
                                    wtlo + 2 * (size_t)D_ * D_, v);

    rope_split<<<(B_ * S_ * H_ * (DK / 2)) / 256, 256>>>(q, k, fc, fs, qh, kh);
    vtrans<<<dim3(S_ / 32, DK / 32, BH_), 256>>>(v, vth);
    sumv_kernel<<<BH_, 256>>>(v, sumvp);

    pass1_mma<<<dim3(S_ / 128, BH_), 256, P1SMEM>>>(qh, kh);
    pass2_mma<<<dim3(S_ / 128, BH_), 256, P2SMEM>>>(vth, sumvp, attn);

    splitX<<<(MS_ * D_) / 256, 256>>>(attn, ahi, alo);
    gemm_mma<<<ggrid, 256, GSMEM>>>(ahi, alo, wthi + 3 * (size_t)D_ * D_,
                                    wtlo + 3 * (size_t)D_ * D_, out);
}

// round 8
// speedup vs baseline: 2.9325x; 1.0847x over previous
#include <cuda_runtime.h>
#include <cuda_bf16.h>
#include <cuda_fp16.h>
#include <math.h>

#define B_  2
#define S_  2048
#define D_  1024
#define H_  16
#define DK  64
#define BH_ (B_*H_)
#define MS_ (B_*S_)          // 4096 rows

// ---------------- scratch (static device arrays; no cudaMalloc) ----------------
__device__ float g_v[(size_t)MS_*D_];
__device__ __half g_sh[(size_t)BH_*S_*S_];      // scaled scores s/8, fp16 (256 MB)
__device__ float g_sumv[BH_*DK];
// bf16 buffers
__device__ __nv_bfloat16 g_xhi[(size_t)MS_*D_];
__device__ __nv_bfloat16 g_xlo[(size_t)MS_*D_];
__device__ __nv_bfloat16 g_ahi[(size_t)MS_*D_];
__device__ __nv_bfloat16 g_alo[(size_t)MS_*D_];
__device__ __nv_bfloat16 g_wthi[4][(size_t)D_*D_];   // W^T hi ([n][k])
__device__ __nv_bfloat16 g_wtlo[4][(size_t)D_*D_];
__device__ __nv_bfloat16 g_qh[(size_t)MS_*D_];       // roped q bf16
__device__ __nv_bfloat16 g_kh[(size_t)MS_*D_];       // roped k bf16
__device__ __nv_bfloat16 g_vth[(size_t)BH_*DK*S_];   // V^T bf16 [b*h][dk][s]

// ================= helpers =================
__device__ __forceinline__ unsigned smem_u32(const void* p) {
    unsigned a;
    asm("{ .reg .u64 t; cvta.to.shared.u64 t, %1; cvt.u32.u64 %0, t; }" : "=r"(a) : "l"(p));
    return a;
}
__device__ __forceinline__ void cp16(unsigned saddr, const void* gaddr) {
    asm volatile("cp.async.cg.shared.global [%0], [%1], 16;" :: "r"(saddr), "l"(gaddr));
}
__device__ __forceinline__ void cp_commit() { asm volatile("cp.async.commit_group;"); }
template <int N>
__device__ __forceinline__ void cp_wait() { asm volatile("cp.async.wait_group %0;" :: "n"(N)); }

__device__ __forceinline__ void mma16816(float* c, const unsigned* a, unsigned b0, unsigned b1) {
    asm volatile("mma.sync.aligned.m16n8k16.row.col.f32.bf16.bf16.f32 "
                 "{%0,%1,%2,%3}, {%4,%5,%6,%7}, {%8,%9}, {%0,%1,%2,%3};"
                 : "+f"(c[0]), "+f"(c[1]), "+f"(c[2]), "+f"(c[3])
                 : "r"(a[0]), "r"(a[1]), "r"(a[2]), "r"(a[3]), "r"(b0), "r"(b1));
}

// ================= split / transform kernels =================
__global__ void splitX(const float* __restrict__ X, __nv_bfloat16* __restrict__ hi,
                       __nv_bfloat16* __restrict__ lo) {
    int i = blockIdx.x * 256 + threadIdx.x;
    float v = X[i];
    __nv_bfloat16 h = __float2bfloat16(v);
    hi[i] = h;
    lo[i] = __float2bfloat16(v - __bfloat162float(h));
}

// W[k][n] -> WT hi/lo [n][k]
__global__ void splitWT(const float* __restrict__ W, __nv_bfloat16* __restrict__ hi,
                        __nv_bfloat16* __restrict__ lo) {
    __shared__ float t[32][33];
    int bx = blockIdx.x * 32, by = blockIdx.y * 32;
    int tx = threadIdx.x & 31, ty = threadIdx.x >> 5;
#pragma unroll
    for (int i = 0; i < 32; i += 8)
        t[ty + i][tx] = W[(size_t)(by + ty + i) * 1024 + bx + tx];
    __syncthreads();
#pragma unroll
    for (int i = 0; i < 32; i += 8) {
        float v = t[tx][ty + i];
        __nv_bfloat16 h = __float2bfloat16(v);
        size_t o = (size_t)(bx + ty + i) * 1024 + by + tx;
        hi[o] = h;
        lo[o] = __float2bfloat16(v - __bfloat162float(h));
    }
}

// V [b][s][h][dk] fp32 -> V^T [b*h][dk][s] bf16
__global__ void vtrans(const float* __restrict__ v, __nv_bfloat16* __restrict__ vth) {
    __shared__ float t[32][33];
    int s0 = blockIdx.x * 32, d0 = blockIdx.y * 32;
    int bh = blockIdx.z, b = bh >> 4, h = bh & 15;
    int tx = threadIdx.x & 31, ty = threadIdx.x >> 5;
#pragma unroll
    for (int i = 0; i < 32; i += 8)
        t[ty + i][tx] = v[((size_t)(b * S_ + s0 + ty + i)) * D_ + h * DK + d0 + tx];
    __syncthreads();
#pragma unroll
    for (int i = 0; i < 32; i += 8)
        vth[((size_t)bh * DK + d0 + ty + i) * S_ + s0 + tx] = __float2bfloat16(t[tx][ty + i]);
}

// sumv[bh][d] = sum_s v[b][s][h][d]  (exact fp32)
__global__ void sumv_kernel(const float* __restrict__ v, float* __restrict__ sumv) {
    int bh = blockIdx.x, b = bh >> 4, h = bh & 15;
    int d = threadIdx.x & 63, sc = threadIdx.x >> 6;
    float s = 0.f;
    for (int i = 0; i < 512; i++)
        s += v[((size_t)(b * S_ + sc * 512 + i)) * D_ + h * DK + d];
    __shared__ float red[256];
    red[threadIdx.x] = s;
    __syncthreads();
    if (sc == 0) sumv[bh * DK + d] = red[d] + red[64 + d] + red[128 + d] + red[192 + d];
}

// ================= 3-term projection GEMM (Wv, Wo) =================
#define SA    40
#define TILEB (128 * SA * 2)
#define BUFB  (4 * TILEB)
#define GSMEM (2 * BUFB)

__global__ __launch_bounds__(256, 1) void gemm_mma(const __nv_bfloat16* __restrict__ Ahi,
                                                   const __nv_bfloat16* __restrict__ Alo,
                                                   const __nv_bfloat16* __restrict__ Bhi,
                                                   const __nv_bfloat16* __restrict__ Blo,
                                                   float* __restrict__ C) {
    extern __shared__ char smc[];
    const int tid = threadIdx.x, lane = tid & 31, wid = tid >> 5;
    const int wm = wid & 3, wn = wid >> 2;
    const int grp = lane >> 2, qid = lane & 3;
    const int m0 = blockIdx.y * 128, n0 = blockIdx.x * 128;
    const unsigned sb = smem_u32(smc);

    const __nv_bfloat16* srcs[4] = {Ahi, Alo, Bhi, Blo};
    const int r0s[4] = {m0, m0, n0, n0};

    float acc[2][8][4];
#pragma unroll
    for (int mt = 0; mt < 2; mt++)
#pragma unroll
        for (int nt = 0; nt < 8; nt++)
#pragma unroll
            for (int e = 0; e < 4; e++) acc[mt][nt][e] = 0.f;

    {
#pragma unroll
        for (int t = 0; t < 4; t++)
#pragma unroll
            for (int u = 0; u < 2; u++) {
                int idx = tid * 2 + u;
                int row = idx >> 2, seg = idx & 3;
                cp16(sb + t * TILEB + row * 80 + seg * 16,
                     srcs[t] + (size_t)(r0s[t] + row) * 1024 + seg * 8);
            }
        cp_commit();
    }

    for (int ch = 0; ch < 32; ch++) {
        const int buf = ch & 1;
        if (ch < 31) {
            const int k0 = (ch + 1) * 32, nbuf = (ch + 1) & 1;
#pragma unroll
            for (int t = 0; t < 4; t++)
#pragma unroll
                for (int u = 0; u < 2; u++) {
                    int idx = tid * 2 + u;
                    int row = idx >> 2, seg = idx & 3;
                    cp16(sb + nbuf * BUFB + t * TILEB + row * 80 + seg * 16,
                         srcs[t] + (size_t)(r0s[t] + row) * 1024 + k0 + seg * 8);
                }
            cp_commit();
            cp_wait<1>();
        } else {
            cp_wait<0>();
        }
        __syncthreads();

        const __nv_bfloat16* Ah = (const __nv_bfloat16*)(smc + buf * BUFB);
        const __nv_bfloat16* Al = Ah + 128 * SA;
        const __nv_bfloat16* Bh = Ah + 2 * 128 * SA;
        const __nv_bfloat16* Bl = Ah + 3 * 128 * SA;

#pragma unroll
        for (int kk = 0; kk < 32; kk += 16) {
            unsigned afh[2][4], afl[2][4];
#pragma unroll
            for (int mt = 0; mt < 2; mt++) {
                int r = wm * 32 + mt * 16 + grp;
                afh[mt][0] = *(const unsigned*)&Ah[r * SA + kk + qid * 2];
                afh[mt][1] = *(const unsigned*)&Ah[(r + 8) * SA + kk + qid * 2];
                afh[mt][2] = *(const unsigned*)&Ah[r * SA + kk + 8 + qid * 2];
                afh[mt][3] = *(const unsigned*)&Ah[(r + 8) * SA + kk + 8 + qid * 2];
                afl[mt][0] = *(const unsigned*)&Al[r * SA + kk + qid * 2];
                afl[mt][1] = *(const unsigned*)&Al[(r + 8) * SA + kk + qid * 2];
                afl[mt][2] = *(const unsigned*)&Al[r * SA + kk + 8 + qid * 2];
                afl[mt][3] = *(const unsigned*)&Al[(r + 8) * SA + kk + 8 + qid * 2];
            }
#pragma unroll
            for (int nt = 0; nt < 8; nt++) {
                int c = wn * 64 + nt * 8 + grp;
                unsigned bh0 = *(const unsigned*)&Bh[c * SA + kk + qid * 2];
                unsigned bh1 = *(const unsigned*)&Bh[c * SA + kk + 8 + qid * 2];
                unsigned bl0 = *(const unsigned*)&Bl[c * SA + kk + qid * 2];
                unsigned bl1 = *(const unsigned*)&Bl[c * SA + kk + 8 + qid * 2];
#pragma unroll
                for (int mt = 0; mt < 2; mt++) {
                    mma16816(acc[mt][nt], afh[mt], bh0, bh1);
                    mma16816(acc[mt][nt], afh[mt], bl0, bl1);
                    mma16816(acc[mt][nt], afl[mt], bh0, bh1);
                }
            }
        }
        __syncthreads();
    }

#pragma unroll
    for (int mt = 0; mt < 2; mt++) {
        int r = m0 + wm * 32 + mt * 16 + grp;
#pragma unroll
        for (int nt = 0; nt < 8; nt++) {
            int c = n0 + wn * 64 + nt * 8 + qid * 2;
            *(float2*)&C[(size_t)r * 1024 + c]       = make_float2(acc[mt][nt][0], acc[mt][nt][1]);
            *(float2*)&C[(size_t)(r + 8) * 1024 + c] = make_float2(acc[mt][nt][2], acc[mt][nt][3]);
        }
    }
}

// ================= 1-term GEMM + fused RoPE (Wq, Wk) -> bf16 =================
#define B1B (2 * TILEB)
#define G1SMEM (2 * B1B)

__global__ __launch_bounds__(256, 1) void gemm_rope(const __nv_bfloat16* __restrict__ Ahi,
                                                    const __nv_bfloat16* __restrict__ Bhi,
                                                    const float* __restrict__ fc,
                                                    const float* __restrict__ fs,
                                                    __nv_bfloat16* __restrict__ dst) {
    extern __shared__ char smc[];
    const int tid = threadIdx.x, lane = tid & 31, wid = tid >> 5;
    const int wm = wid & 3, wn = wid >> 2;
    const int grp = lane >> 2, qid = lane & 3;
    const int m0 = blockIdx.y * 128, n0 = blockIdx.x * 128;
    const unsigned sb = smem_u32(smc);

    const __nv_bfloat16* srcs[2] = {Ahi, Bhi};
    const int r0s[2] = {m0, n0};

    float acc[2][8][4];
#pragma unroll
    for (int mt = 0; mt < 2; mt++)
#pragma unroll
        for (int nt = 0; nt < 8; nt++)
#pragma unroll
            for (int e = 0; e < 4; e++) acc[mt][nt][e] = 0.f;

    {
#pragma unroll
        for (int t = 0; t < 2; t++)
#pragma unroll
            for (int u = 0; u < 2; u++) {
                int idx = tid * 2 + u;
                int row = idx >> 2, seg = idx & 3;
                cp16(sb + t * TILEB + row * 80 + seg * 16,
                     srcs[t] + (size_t)(r0s[t] + row) * 1024 + seg * 8);
            }
        cp_commit();
    }

    for (int ch = 0; ch < 32; ch++) {
        const int buf = ch & 1;
        if (ch < 31) {
            const int k0 = (ch + 1) * 32, nbuf = (ch + 1) & 1;
#pragma unroll
            for (int t = 0; t < 2; t++)
#pragma unroll
                for (int u = 0; u < 2; u++) {
                    int idx = tid * 2 + u;
                    int row = idx >> 2, seg = idx & 3;
                    cp16(sb + nbuf * B1B + t * TILEB + row * 80 + seg * 16,
                         srcs[t] + (size_t)(r0s[t] + row) * 1024 + k0 + seg * 8);
                }
            cp_commit();
            cp_wait<1>();
        } else {
            cp_wait<0>();
        }
        __syncthreads();

        const __nv_bfloat16* Ah = (const __nv_bfloat16*)(smc + buf * B1B);
        const __nv_bfloat16* Bh = Ah + 128 * SA;

#pragma unroll
        for (int kk = 0; kk < 32; kk += 16) {
            unsigned afh[2][4];
#pragma unroll
            for (int mt = 0; mt < 2; mt++) {
                int r = wm * 32 + mt * 16 + grp;
                afh[mt][0] = *(const unsigned*)&Ah[r * SA + kk + qid * 2];
                afh[mt][1] = *(const unsigned*)&Ah[(r + 8) * SA + kk + qid * 2];
                afh[mt][2] = *(const unsigned*)&Ah[r * SA + kk + 8 + qid * 2];
                afh[mt][3] = *(const unsigned*)&Ah[(r + 8) * SA + kk + 8 + qid * 2];
            }
#pragma unroll
            for (int nt = 0; nt < 8; nt++) {
                int c = wn * 64 + nt * 8 + grp;
                unsigned bh0 = *(const unsigned*)&Bh[c * SA + kk + qid * 2];
                unsigned bh1 = *(const unsigned*)&Bh[c * SA + kk + 8 + qid * 2];
#pragma unroll
                for (int mt = 0; mt < 2; mt++)
                    mma16816(acc[mt][nt], afh[mt], bh0, bh1);
            }
        }
        __syncthreads();
    }

    // fused RoPE epilogue -> bf16 (pairs (c, c+1) are (re, im) within head)
#pragma unroll
    for (int mt = 0; mt < 2; mt++) {
        int r = m0 + wm * 32 + mt * 16 + grp;
        int s = r & (S_ - 1);
#pragma unroll
        for (int nt = 0; nt < 8; nt++) {
            int c = n0 + wn * 64 + nt * 8 + qid * 2;
            int ii = (c & 63) >> 1;
            float c0 = fc[s * 32 + ii],       s0 = fs[s * 32 + ii];
            float c1 = fc[(s + 8) * 32 + ii], s1 = fs[(s + 8) * 32 + ii];
            float re0 = acc[mt][nt][0], im0 = acc[mt][nt][1];
            float re1 = acc[mt][nt][2], im1 = acc[mt][nt][3];
            __nv_bfloat162 p0, p1;
            p0.x = __float2bfloat16(re0 * c0 - im0 * s0);
            p0.y = __float2bfloat16(re0 * s0 + im0 * c0);
            p1.x = __float2bfloat16(re1 * c1 - im1 * s1);
            p1.y = __float2bfloat16(re1 * s1 + im1 * c1);
            *(__nv_bfloat162*)&dst[(size_t)r * 1024 + c]       = p0;
            *(__nv_bfloat162*)&dst[(size_t)(r + 8) * 1024 + c] = p1;
        }
    }
}

// ================= fused attention: pass1 + pass2 in one kernel =================
#define P1S   72
#define P1ROW (P1S * 2)
#define P1T   (128 * P1ROW)   // 18432
#define P2S   136
#define P2ROW (P2S * 2)
#define P2TT  (128 * P2ROW)   // 34816
#define P2VT  (64 * P2ROW)    // 17408
#define FA_ZBUF (3 * P1T)           // 55296, 1024 B
#define FA_SZ   (3 * P1T + 1024)    // 56320, 512 B
#define FASMEM  (3 * P1T + 2048)    // 57344

__global__ __launch_bounds__(256, 1) void attn_fused(const __nv_bfloat16* __restrict__ qh,
                                                     const __nv_bfloat16* __restrict__ kh,
                                                     const __nv_bfloat16* __restrict__ vth,
                                                     const float* __restrict__ sumv,
                                                     __nv_bfloat16* __restrict__ ahi,
                                                     __nv_bfloat16* __restrict__ alo) {
    extern __shared__ char smc[];
    const unsigned sb = smem_u32(smc);
    const int tid = threadIdx.x, lane = tid & 31, wid = tid >> 5;
    const int wm = wid & 3, wn = wid >> 2;
    const int grp = lane >> 2, qid = lane & 3;
    const int bh = blockIdx.y, b = bh >> 4, h = bh & 15;
    const int q0 = blockIdx.x * 128;
    const int ty = tid >> 4, tx = tid & 15;
    float* zbuf = (float*)(smc + FA_ZBUF);
    float* sz   = (float*)(smc + FA_SZ);

    // ======== phase A: s' = QK^T/8 -> fp16 gmem (L2-resident), z -> smem ========
    {
#pragma unroll
        for (int u = 0; u < 4; u++) {
            int idx = tid * 4 + u;
            int row = idx >> 3, ch = idx & 7;
            cp16(sb + row * P1ROW + ch * 16,
                 qh + ((size_t)(b * S_ + q0 + row)) * D_ + h * DK + ch * 8);
        }
#pragma unroll
        for (int u = 0; u < 4; u++) {
            int idx = tid * 4 + u;
            int row = idx >> 3, ch = idx & 7;
            cp16(sb + P1T + row * P1ROW + ch * 16,
                 kh + ((size_t)(b * S_ + row)) * D_ + h * DK + ch * 8);
        }
        cp_commit();
    }
    cp_wait<0>();
    __syncthreads();

    unsigned qf[2][4][4];
    {
        const __nv_bfloat16* Qh = (const __nv_bfloat16*)smc;
#pragma unroll
        for (int mt = 0; mt < 2; mt++) {
            int r = wm * 32 + mt * 16 + grp;
#pragma unroll
            for (int kk = 0; kk < 4; kk++) {
                int c0 = kk * 16 + qid * 2;
                qf[mt][kk][0] = *(const unsigned*)&Qh[r * P1S + c0];
                qf[mt][kk][1] = *(const unsigned*)&Qh[(r + 8) * P1S + c0];
                qf[mt][kk][2] = *(const unsigned*)&Qh[r * P1S + c0 + 8];
                qf[mt][kk][3] = *(const unsigned*)&Qh[(r + 8) * P1S + c0 + 8];
            }
        }
    }

    float zacc[2][2] = {{0.f, 0.f}, {0.f, 0.f}};

    for (int kt = 0; kt < 16; kt++) {
        const int buf = kt & 1;
        if (kt < 15) {
            const int nbuf = (kt + 1) & 1;
#pragma unroll
            for (int u = 0; u < 4; u++) {
                int idx = tid * 4 + u;
                int row = idx >> 3, ch = idx & 7;
                cp16(sb + (1 + nbuf) * P1T + row * P1ROW + ch * 16,
                     kh + ((size_t)(b * S_ + (kt + 1) * 128 + row)) * D_ + h * DK + ch * 8);
            }
            cp_commit();
            cp_wait<1>();
        } else {
            cp_wait<0>();
        }
        __syncthreads();

        const __nv_bfloat16* Kh = (const __nv_bfloat16*)(smc + (1 + buf) * P1T);

        float acc[2][8][4];
#pragma unroll
        for (int mt = 0; mt < 2; mt++)
#pragma unroll
            for (int nt = 0; nt < 8; nt++)
#pragma unroll
                for (int e = 0; e < 4; e++) acc[mt][nt][e] = 0.f;

#pragma unroll
        for (int kk = 0; kk < 4; kk++) {
#pragma unroll
            for (int nt = 0; nt < 8; nt++) {
                int c = wn * 64 + nt * 8 + grp;
                int c0 = kk * 16 + qid * 2;
                unsigned bh0 = *(const unsigned*)&Kh[c * P1S + c0];
                unsigned bh1 = *(const unsigned*)&Kh[c * P1S + c0 + 8];
#pragma unroll
                for (int mt = 0; mt < 2; mt++)
                    mma16816(acc[mt][nt], qf[mt][kk], bh0, bh1);
            }
        }

#pragma unroll
        for (int mt = 0; mt < 2; mt++) {
            int r = q0 + wm * 32 + mt * 16 + grp;
#pragma unroll
            for (int nt = 0; nt < 8; nt++) {
                int c = kt * 128 + wn * 64 + nt * 8 + qid * 2;
                float s0 = acc[mt][nt][0] * 0.125f, s1 = acc[mt][nt][1] * 0.125f;
                float s2 = acc[mt][nt][2] * 0.125f, s3 = acc[mt][nt][3] * 0.125f;
                *(__half2*)&g_sh[((size_t)bh * S_ + r) * S_ + c]     = __floats2half2_rn(s0, s1);
                *(__half2*)&g_sh[((size_t)bh * S_ + r + 8) * S_ + c] = __floats2half2_rn(s2, s3);
                zacc[mt][0] += __expf(s0) + __expf(s1);
                zacc[mt][1] += __expf(s2) + __expf(s3);
            }
        }
        __syncthreads();
    }

#pragma unroll
    for (int mt = 0; mt < 2; mt++)
#pragma unroll
        for (int hf = 0; hf < 2; hf++) {
            float z = zacc[mt][hf];
            z += __shfl_xor_sync(0xffffffffu, z, 1);
            z += __shfl_xor_sync(0xffffffffu, z, 2);
            if (qid == 0) zbuf[wn * 128 + wm * 32 + mt * 16 + hf * 8 + grp] = z;
        }
    __syncthreads();
    if (tid < 128) sz[tid] = zbuf[tid] + zbuf[128 + tid];
    __syncthreads();

    // ======== phase B: p' = expm1(exp(s')/z); out = (sumv + p'V)/(2048+sum p') ====
    __nv_bfloat16* Th = (__nv_bfloat16*)smc;
    const __nv_bfloat16* Vh = (const __nv_bfloat16*)(smc + P2TT);
    float* tsums = (float*)(smc + P2TT + P2VT);

    float iz[8], tsum[8];
#pragma unroll
    for (int i = 0; i < 8; i++) {
        iz[i] = 1.0f / sz[ty * 8 + i];
        tsum[i] = 0.f;
    }

    float acc2[2][4][4];
#pragma unroll
    for (int mt = 0; mt < 2; mt++)
#pragma unroll
        for (int nt = 0; nt < 4; nt++)
#pragma unroll
            for (int e = 0; e < 4; e++) acc2[mt][nt][e] = 0.f;

    for (int kt = 0; kt < 16; kt++) {
        const int k0 = kt * 128;
        {
#pragma unroll
            for (int u = 0; u < 4; u++) {
                int idx = tid * 4 + u;                 // 0..1023
                int row = idx >> 4, ch = idx & 15;
                cp16(sb + P2TT + row * P2ROW + ch * 16,
                     vth + ((size_t)bh * DK + row) * S_ + k0 + ch * 8);
            }
            cp_commit();
        }
#pragma unroll
        for (int i = 0; i < 8; i++) {
            int r = ty * 8 + i;
#pragma unroll
            for (int hf = 0; hf < 2; hf++) {
                int c = hf * 64 + tx * 4;
                struct alignas(8) H4 { __half2 a, b; };
                H4 s4 = *(const H4*)&g_sh[((size_t)bh * S_ + q0 + r) * S_ + k0 + c];
                float2 f01 = __half22float2(s4.a);
                float2 f23 = __half22float2(s4.b);
                float p0 = __expf(f01.x) * iz[i];
                float p1 = __expf(f01.y) * iz[i];
                float p2 = __expf(f23.x) * iz[i];
                float p3 = __expf(f23.y) * iz[i];
                float t0 = fmaf(0.5f * p0, p0, p0);
                float t1 = fmaf(0.5f * p1, p1, p1);
                float t2 = fmaf(0.5f * p2, p2, p2);
                float t3 = fmaf(0.5f * p3, p3, p3);
                tsum[i] += (t0 + t1) + (t2 + t3);
                __nv_bfloat162 h01, h23;
                h01.x = __float2bfloat16(t0); h01.y = __float2bfloat16(t1);
                h23.x = __float2bfloat16(t2); h23.y = __float2bfloat16(t3);
                *(__nv_bfloat162*)&Th[r * P2S + c]     = h01;
                *(__nv_bfloat162*)&Th[r * P2S + c + 2] = h23;
            }
        }
        cp_wait<0>();
        __syncthreads();

#pragma unroll
        for (int kk = 0; kk < 8; kk++) {
            unsigned af[2][4];
            int c0 = kk * 16 + qid * 2;
#pragma unroll
            for (int mt = 0; mt < 2; mt++) {
                int r = wm * 32 + mt * 16 + grp;
                af[mt][0] = *(const unsigned*)&Th[r * P2S + c0];
                af[mt][1] = *(const unsigned*)&Th[(r + 8) * P2S + c0];
                af[mt][2] = *(const unsigned*)&Th[r * P2S + c0 + 8];
                af[mt][3] = *(const unsigned*)&Th[(r + 8) * P2S + c0 + 8];
            }
#pragma unroll
            for (int nt = 0; nt < 4; nt++) {
                int c = wn * 32 + nt * 8 + grp;
                unsigned bh0 = *(const unsigned*)&Vh[c * P2S + c0];
                unsigned bh1 = *(const unsigned*)&Vh[c * P2S + c0 + 8];
#pragma unroll
                for (int mt = 0; mt < 2; mt++)
                    mma16816(acc2[mt][nt], af[mt], bh0, bh1);
            }
        }
        __syncthreads();
    }

#pragma unroll
    for (int i = 0; i < 8; i++) {
        float s = tsum[i];
        s += __shfl_xor_sync(0xffffffffu, s, 1);
        s += __shfl_xor_sync(0xffffffffu, s, 2);
        s += __shfl_xor_sync(0xffffffffu, s, 4);
        s += __shfl_xor_sync(0xffffffffu, s, 8);
        if (tx == 0) tsums[ty * 8 + i] = s;
    }
    __syncthreads();

    // epilogue: out = (sumv + acc) / (2048 + sum p'), written as bf16 split
#pragma unroll
    for (int mt = 0; mt < 2; mt++) {
        int rl0 = wm * 32 + mt * 16 + grp;
        float r0 = 1.0f / (2048.0f + tsums[rl0]);
        float r1 = 1.0f / (2048.0f + tsums[rl0 + 8]);
#pragma unroll
        for (int nt = 0; nt < 4; nt++) {
            int dcol = wn * 32 + nt * 8 + qid * 2;
            float sv0 = sumv[bh * DK + dcol];
            float sv1 = sumv[bh * DK + dcol + 1];
            int c = h * DK + dcol;
            size_t o0 = ((size_t)(b * S_ + q0 + rl0)) * D_ + c;
            size_t o1 = ((size_t)(b * S_ + q0 + rl0 + 8)) * D_ + c;
            float v00 = (sv0 + acc2[mt][nt][0]) * r0;
            float v01 = (sv1 + acc2[mt][nt][1]) * r0;
            float v10 = (sv0 + acc2[mt][nt][2]) * r1;
            float v11 = (sv1 + acc2[mt][nt][3]) * r1;
            __nv_bfloat162 h0, l0, h1, l1;
            h0.x = __float2bfloat16(v00); l0.x = __float2bfloat16(v00 - __bfloat162float(h0.x));
            h0.y = __float2bfloat16(v01); l0.y = __float2bfloat16(v01 - __bfloat162float(h0.y));
            h1.x = __float2bfloat16(v10); l1.x = __float2bfloat16(v10 - __bfloat162float(h1.x));
            h1.y = __float2bfloat16(v11); l1.y = __float2bfloat16(v11 - __bfloat162float(h1.y));
            *(__nv_bfloat162*)&ahi[o0] = h0;
            *(__nv_bfloat162*)&alo[o0] = l0;
            *(__nv_bfloat162*)&ahi[o1] = h1;
            *(__nv_bfloat162*)&alo[o1] = l1;
        }
    }
}

// ---------------- launch ----------------
extern "C" void kernel_launch(void* const* d_in, const int* in_sizes, int n_in,
                              void* d_out, int out_size) {
    const float* x  = (const float*)d_in[0];
    const float* fc = (const float*)d_in[1];
    const float* fs = (const float*)d_in[2];
    const float* W[4] = {(const float*)d_in[3], (const float*)d_in[4],
                         (const float*)d_in[5], (const float*)d_in[6]};
    float* out = (float*)d_out;

    float *v, *sumvp;
    __nv_bfloat16 *xhi, *xlo, *ahi, *alo, *wthi, *wtlo, *qh, *kh, *vth;
    cudaGetSymbolAddress((void**)&v, g_v);
    cudaGetSymbolAddress((void**)&sumvp, g_sumv);
    cudaGetSymbolAddress((void**)&xhi, g_xhi);
    cudaGetSymbolAddress((void**)&xlo, g_xlo);
    cudaGetSymbolAddress((void**)&ahi, g_ahi);
    cudaGetSymbolAddress((void**)&alo, g_alo);
    cudaGetSymbolAddress((void**)&wthi, g_wthi);
    cudaGetSymbolAddress((void**)&wtlo, g_wtlo);
    cudaGetSymbolAddress((void**)&qh, g_qh);
    cudaGetSymbolAddress((void**)&kh, g_kh);
    cudaGetSymbolAddress((void**)&vth, g_vth);

    cudaFuncSetAttribute(gemm_mma, cudaFuncAttributeMaxDynamicSharedMemorySize, GSMEM);
    cudaFuncSetAttribute(gemm_rope, cudaFuncAttributeMaxDynamicSharedMemorySize, G1SMEM);
    cudaFuncSetAttribute(attn_fused, cudaFuncAttributeMaxDynamicSharedMemorySize, FASMEM);

    splitX<<<(MS_ * D_) / 256, 256>>>(x, xhi, xlo);
    for (int i = 0; i < 4; i++)
        splitWT<<<dim3(32, 32), 256>>>(W[i], wthi + (size_t)i * D_ * D_,
                                       wtlo + (size_t)i * D_ * D_);

    dim3 ggrid(8, 32);
    gemm_rope<<<ggrid, 256, G1SMEM>>>(xhi, wthi + 0 * (size_t)D_ * D_, fc, fs, qh);
    gemm_rope<<<ggrid, 256, G1SMEM>>>(xhi, wthi + 1 * (size_t)D_ * D_, fc, fs, kh);
    gemm_mma<<<ggrid, 256, GSMEM>>>(xhi, xlo, wthi + 2 * (size_t)D_ * D_,
                                    wtlo + 2 * (size_t)D_ * D_, v);

    vtrans<<<dim3(S_ / 32, DK / 32, BH_), 256>>>(v, vth);
    sumv_kernel<<<BH_, 256>>>(v, sumvp);

    attn_fused<<<dim3(S_ / 128, BH_), 256, FASMEM>>>(qh, kh, vth, sumvp, ahi, alo);

    gemm_mma<<<ggrid, 256, GSMEM>>>(ahi, alo, wthi + 3 * (size_t)D_ * D_,
                                    wtlo + 3 * (size_t)D_ * D_, out);
}

// round 9
// speedup vs baseline: 3.5922x; 1.2250x over previous
#include <cuda_runtime.h>
#include <cuda_bf16.h>
#include <cuda_fp16.h>
#include <math.h>

#define B_  2
#define S_  2048
#define D_  1024
#define H_  16
#define DK  64
#define BH_ (B_*H_)
#define MS_ (B_*S_)          // 4096 rows

// ---------------- scratch (static device arrays; no cudaMalloc) ----------------
__device__ float g_v[(size_t)MS_*D_];
__device__ __half g_sh[(size_t)BH_*S_*S_];      // scaled scores s/8, fp16 (256 MB)
__device__ float g_sumv[BH_*DK];
__device__ __half g_xh[(size_t)MS_*D_];          // x fp16
__device__ __half g_ah[(size_t)MS_*D_];          // attn fp16
__device__ __half g_wt[4][(size_t)D_*D_];        // W^T fp16 ([n][k])
__device__ __half g_qh[(size_t)MS_*D_];          // roped q fp16
__device__ __half g_kh[(size_t)MS_*D_];          // roped k fp16
__device__ __half g_vth[(size_t)BH_*DK*S_];      // V^T fp16 [b*h][dk][s]

// ================= helpers =================
__device__ __forceinline__ unsigned smem_u32(const void* p) {
    unsigned a;
    asm("{ .reg .u64 t; cvta.to.shared.u64 t, %1; cvt.u32.u64 %0, t; }" : "=r"(a) : "l"(p));
    return a;
}
__device__ __forceinline__ void cp16(unsigned saddr, const void* gaddr) {
    asm volatile("cp.async.cg.shared.global [%0], [%1], 16;" :: "r"(saddr), "l"(gaddr));
}
__device__ __forceinline__ void cp_commit() { asm volatile("cp.async.commit_group;"); }
template <int N>
__device__ __forceinline__ void cp_wait() { asm volatile("cp.async.wait_group %0;" :: "n"(N)); }

__device__ __forceinline__ void mma16816(float* c, const unsigned* a, unsigned b0, unsigned b1) {
    asm volatile("mma.sync.aligned.m16n8k16.row.col.f32.f16.f16.f32 "
                 "{%0,%1,%2,%3}, {%4,%5,%6,%7}, {%8,%9}, {%0,%1,%2,%3};"
                 : "+f"(c[0]), "+f"(c[1]), "+f"(c[2]), "+f"(c[3])
                 : "r"(a[0]), "r"(a[1]), "r"(a[2]), "r"(a[3]), "r"(b0), "r"(b1));
}

// ================= convert / transform kernels =================
__global__ void convX(const float* __restrict__ X, __half* __restrict__ out) {
    int i = blockIdx.x * 256 + threadIdx.x;
    out[i] = __float2half(X[i]);
}

// W[k][n] -> WT fp16 [n][k]
__global__ void convWT(const float* __restrict__ W, __half* __restrict__ wt) {
    __shared__ float t[32][33];
    int bx = blockIdx.x * 32, by = blockIdx.y * 32;
    int tx = threadIdx.x & 31, ty = threadIdx.x >> 5;
#pragma unroll
    for (int i = 0; i < 32; i += 8)
        t[ty + i][tx] = W[(size_t)(by + ty + i) * 1024 + bx + tx];
    __syncthreads();
#pragma unroll
    for (int i = 0; i < 32; i += 8)
        wt[(size_t)(bx + ty + i) * 1024 + by + tx] = __float2half(t[tx][ty + i]);
}

// V [b][s][h][dk] fp32 -> V^T [b*h][dk][s] fp16
__global__ void vtrans(const float* __restrict__ v, __half* __restrict__ vth) {
    __shared__ float t[32][33];
    int s0 = blockIdx.x * 32, d0 = blockIdx.y * 32;
    int bh = blockIdx.z, b = bh >> 4, h = bh & 15;
    int tx = threadIdx.x & 31, ty = threadIdx.x >> 5;
#pragma unroll
    for (int i = 0; i < 32; i += 8)
        t[ty + i][tx] = v[((size_t)(b * S_ + s0 + ty + i)) * D_ + h * DK + d0 + tx];
    __syncthreads();
#pragma unroll
    for (int i = 0; i < 32; i += 8)
        vth[((size_t)bh * DK + d0 + ty + i) * S_ + s0 + tx] = __float2half(t[tx][ty + i]);
}

// sumv[bh][d] = sum_s v[b][s][h][d]  (exact fp32)
__global__ void sumv_kernel(const float* __restrict__ v, float* __restrict__ sumv) {
    int bh = blockIdx.x, b = bh >> 4, h = bh & 15;
    int d = threadIdx.x & 63, sc = threadIdx.x >> 6;
    float s = 0.f;
    for (int i = 0; i < 512; i++)
        s += v[((size_t)(b * S_ + sc * 512 + i)) * D_ + h * DK + d];
    __shared__ float red[256];
    red[threadIdx.x] = s;
    __syncthreads();
    if (sc == 0) sumv[bh * DK + d] = red[d] + red[64 + d] + red[128 + d] + red[192 + d];
}

// ================= 1-term fp16 GEMM common tiling =================
#define SA    40                    // smem row stride in halves (80 B)
#define TILEB (128 * SA * 2)        // 10240 B per tile
#define B1B   (2 * TILEB)
#define G1SMEM (2 * B1B)

// plain: C fp32 = A fp16 @ W^T fp16
__global__ __launch_bounds__(256, 1) void gemm_f16(const __half* __restrict__ Ah_,
                                                   const __half* __restrict__ Bh_,
                                                   float* __restrict__ C) {
    extern __shared__ char smc[];
    const int tid = threadIdx.x, lane = tid & 31, wid = tid >> 5;
    const int wm = wid & 3, wn = wid >> 2;
    const int grp = lane >> 2, qid = lane & 3;
    const int m0 = blockIdx.y * 128, n0 = blockIdx.x * 128;
    const unsigned sb = smem_u32(smc);

    const __half* srcs[2] = {Ah_, Bh_};
    const int r0s[2] = {m0, n0};

    float acc[2][8][4];
#pragma unroll
    for (int mt = 0; mt < 2; mt++)
#pragma unroll
        for (int nt = 0; nt < 8; nt++)
#pragma unroll
            for (int e = 0; e < 4; e++) acc[mt][nt][e] = 0.f;

    {
#pragma unroll
        for (int t = 0; t < 2; t++)
#pragma unroll
            for (int u = 0; u < 2; u++) {
                int idx = tid * 2 + u;
                int row = idx >> 2, seg = idx & 3;
                cp16(sb + t * TILEB + row * 80 + seg * 16,
                     srcs[t] + (size_t)(r0s[t] + row) * 1024 + seg * 8);
            }
        cp_commit();
    }

    for (int ch = 0; ch < 32; ch++) {
        const int buf = ch & 1;
        if (ch < 31) {
            const int k0 = (ch + 1) * 32, nbuf = (ch + 1) & 1;
#pragma unroll
            for (int t = 0; t < 2; t++)
#pragma unroll
                for (int u = 0; u < 2; u++) {
                    int idx = tid * 2 + u;
                    int row = idx >> 2, seg = idx & 3;
                    cp16(sb + nbuf * B1B + t * TILEB + row * 80 + seg * 16,
                         srcs[t] + (size_t)(r0s[t] + row) * 1024 + k0 + seg * 8);
                }
            cp_commit();
            cp_wait<1>();
        } else {
            cp_wait<0>();
        }
        __syncthreads();

        const __half* Ah = (const __half*)(smc + buf * B1B);
        const __half* Bh = Ah + 128 * SA;

#pragma unroll
        for (int kk = 0; kk < 32; kk += 16) {
            unsigned af[2][4];
#pragma unroll
            for (int mt = 0; mt < 2; mt++) {
                int r = wm * 32 + mt * 16 + grp;
                af[mt][0] = *(const unsigned*)&Ah[r * SA + kk + qid * 2];
                af[mt][1] = *(const unsigned*)&Ah[(r + 8) * SA + kk + qid * 2];
                af[mt][2] = *(const unsigned*)&Ah[r * SA + kk + 8 + qid * 2];
                af[mt][3] = *(const unsigned*)&Ah[(r + 8) * SA + kk + 8 + qid * 2];
            }
#pragma unroll
            for (int nt = 0; nt < 8; nt++) {
                int c = wn * 64 + nt * 8 + grp;
                unsigned b0 = *(const unsigned*)&Bh[c * SA + kk + qid * 2];
                unsigned b1 = *(const unsigned*)&Bh[c * SA + kk + 8 + qid * 2];
#pragma unroll
                for (int mt = 0; mt < 2; mt++)
                    mma16816(acc[mt][nt], af[mt], b0, b1);
            }
        }
        __syncthreads();
    }

#pragma unroll
    for (int mt = 0; mt < 2; mt++) {
        int r = m0 + wm * 32 + mt * 16 + grp;
#pragma unroll
        for (int nt = 0; nt < 8; nt++) {
            int c = n0 + wn * 64 + nt * 8 + qid * 2;
            *(float2*)&C[(size_t)r * 1024 + c]       = make_float2(acc[mt][nt][0], acc[mt][nt][1]);
            *(float2*)&C[(size_t)(r + 8) * 1024 + c] = make_float2(acc[mt][nt][2], acc[mt][nt][3]);
        }
    }
}

// with fused RoPE epilogue -> fp16 (for Wq, Wk)
__global__ __launch_bounds__(256, 1) void gemm_rope(const __half* __restrict__ Ah_,
                                                    const __half* __restrict__ Bh_,
                                                    const float* __restrict__ fc,
                                                    const float* __restrict__ fs,
                                                    __half* __restrict__ dst) {
    extern __shared__ char smc[];
    const int tid = threadIdx.x, lane = tid & 31, wid = tid >> 5;
    const int wm = wid & 3, wn = wid >> 2;
    const int grp = lane >> 2, qid = lane & 3;
    const int m0 = blockIdx.y * 128, n0 = blockIdx.x * 128;
    const unsigned sb = smem_u32(smc);

    const __half* srcs[2] = {Ah_, Bh_};
    const int r0s[2] = {m0, n0};

    float acc[2][8][4];
#pragma unroll
    for (int mt = 0; mt < 2; mt++)
#pragma unroll
        for (int nt = 0; nt < 8; nt++)
#pragma unroll
            for (int e = 0; e < 4; e++) acc[mt][nt][e] = 0.f;

    {
#pragma unroll
        for (int t = 0; t < 2; t++)
#pragma unroll
            for (int u = 0; u < 2; u++) {
                int idx = tid * 2 + u;
                int row = idx >> 2, seg = idx & 3;
                cp16(sb + t * TILEB + row * 80 + seg * 16,
                     srcs[t] + (size_t)(r0s[t] + row) * 1024 + seg * 8);
            }
        cp_commit();
    }

    for (int ch = 0; ch < 32; ch++) {
        const int buf = ch & 1;
        if (ch < 31) {
            const int k0 = (ch + 1) * 32, nbuf = (ch + 1) & 1;
#pragma unroll
            for (int t = 0; t < 2; t++)
#pragma unroll
                for (int u = 0; u < 2; u++) {
                    int idx = tid * 2 + u;
                    int row = idx >> 2, seg = idx & 3;
                    cp16(sb + nbuf * B1B + t * TILEB + row * 80 + seg * 16,
                         srcs[t] + (size_t)(r0s[t] + row) * 1024 + k0 + seg * 8);
                }
            cp_commit();
            cp_wait<1>();
        } else {
            cp_wait<0>();
        }
        __syncthreads();

        const __half* Ah = (const __half*)(smc + buf * B1B);
        const __half* Bh = Ah + 128 * SA;

#pragma unroll
        for (int kk = 0; kk < 32; kk += 16) {
            unsigned af[2][4];
#pragma unroll
            for (int mt = 0; mt < 2; mt++) {
                int r = wm * 32 + mt * 16 + grp;
                af[mt][0] = *(const unsigned*)&Ah[r * SA + kk + qid * 2];
                af[mt][1] = *(const unsigned*)&Ah[(r + 8) * SA + kk + qid * 2];
                af[mt][2] = *(const unsigned*)&Ah[r * SA + kk + 8 + qid * 2];
                af[mt][3] = *(const unsigned*)&Ah[(r + 8) * SA + kk + 8 + qid * 2];
            }
#pragma unroll
            for (int nt = 0; nt < 8; nt++) {
                int c = wn * 64 + nt * 8 + grp;
                unsigned b0 = *(const unsigned*)&Bh[c * SA + kk + qid * 2];
                unsigned b1 = *(const unsigned*)&Bh[c * SA + kk + 8 + qid * 2];
#pragma unroll
                for (int mt = 0; mt < 2; mt++)
                    mma16816(acc[mt][nt], af[mt], b0, b1);
            }
        }
        __syncthreads();
    }

    // fused RoPE epilogue -> fp16 (pairs (c, c+1) are (re, im) within head)
#pragma unroll
    for (int mt = 0; mt < 2; mt++) {
        int r = m0 + wm * 32 + mt * 16 + grp;
        int s = r & (S_ - 1);
#pragma unroll
        for (int nt = 0; nt < 8; nt++) {
            int c = n0 + wn * 64 + nt * 8 + qid * 2;
            int ii = (c & 63) >> 1;
            float c0 = fc[s * 32 + ii],       s0 = fs[s * 32 + ii];
            float c1 = fc[(s + 8) * 32 + ii], s1 = fs[(s + 8) * 32 + ii];
            float re0 = acc[mt][nt][0], im0 = acc[mt][nt][1];
            float re1 = acc[mt][nt][2], im1 = acc[mt][nt][3];
            __half2 p0, p1;
            p0.x = __float2half(re0 * c0 - im0 * s0);
            p0.y = __float2half(re0 * s0 + im0 * c0);
            p1.x = __float2half(re1 * c1 - im1 * s1);
            p1.y = __float2half(re1 * s1 + im1 * c1);
            *(__half2*)&dst[(size_t)r * 1024 + c]       = p0;
            *(__half2*)&dst[(size_t)(r + 8) * 1024 + c] = p1;
        }
    }
}

// ================= fused attention: pass1 + pass2 =================
#define P1S   72
#define P1ROW (P1S * 2)
#define P1T   (128 * P1ROW)   // 18432
#define P2S   136
#define P2ROW (P2S * 2)
#define P2TT  (128 * P2ROW)   // 34816
#define P2VT  (64 * P2ROW)    // 17408
#define FA_ZBUF (3 * P1T)
#define FA_SZ   (3 * P1T + 1024)
#define FASMEM  (3 * P1T + 2048)    // 57344

__global__ __launch_bounds__(256, 1) void attn_fused(const __half* __restrict__ qh,
                                                     const __half* __restrict__ kh,
                                                     const __half* __restrict__ vth,
                                                     const float* __restrict__ sumv,
                                                     __half* __restrict__ aout) {
    extern __shared__ char smc[];
    const unsigned sb = smem_u32(smc);
    const int tid = threadIdx.x, lane = tid & 31, wid = tid >> 5;
    const int wm = wid & 3, wn = wid >> 2;
    const int grp = lane >> 2, qid = lane & 3;
    const int bh = blockIdx.y, b = bh >> 4, h = bh & 15;
    const int q0 = blockIdx.x * 128;
    const int ty = tid >> 4, tx = tid & 15;
    float* zbuf = (float*)(smc + FA_ZBUF);
    float* sz   = (float*)(smc + FA_SZ);

    // ======== phase A: s' = QK^T/8 -> fp16 gmem, z -> smem ========
    {
#pragma unroll
        for (int u = 0; u < 4; u++) {
            int idx = tid * 4 + u;
            int row = idx >> 3, ch = idx & 7;
            cp16(sb + row * P1ROW + ch * 16,
                 qh + ((size_t)(b * S_ + q0 + row)) * D_ + h * DK + ch * 8);
        }
#pragma unroll
        for (int u = 0; u < 4; u++) {
            int idx = tid * 4 + u;
            int row = idx >> 3, ch = idx & 7;
            cp16(sb + P1T + row * P1ROW + ch * 16,
                 kh + ((size_t)(b * S_ + row)) * D_ + h * DK + ch * 8);
        }
        cp_commit();
    }
    cp_wait<0>();
    __syncthreads();

    unsigned qf[2][4][4];
    {
        const __half* Qh = (const __half*)smc;
#pragma unroll
        for (int mt = 0; mt < 2; mt++) {
            int r = wm * 32 + mt * 16 + grp;
#pragma unroll
            for (int kk = 0; kk < 4; kk++) {
                int c0 = kk * 16 + qid * 2;
                qf[mt][kk][0] = *(const unsigned*)&Qh[r * P1S + c0];
                qf[mt][kk][1] = *(const unsigned*)&Qh[(r + 8) * P1S + c0];
                qf[mt][kk][2] = *(const unsigned*)&Qh[r * P1S + c0 + 8];
                qf[mt][kk][3] = *(const unsigned*)&Qh[(r + 8) * P1S + c0 + 8];
            }
        }
    }

    float zacc[2][2] = {{0.f, 0.f}, {0.f, 0.f}};

    for (int kt = 0; kt < 16; kt++) {
        const int buf = kt & 1;
        if (kt < 15) {
            const int nbuf = (kt + 1) & 1;
#pragma unroll
            for (int u = 0; u < 4; u++) {
                int idx = tid * 4 + u;
                int row = idx >> 3, ch = idx & 7;
                cp16(sb + (1 + nbuf) * P1T + row * P1ROW + ch * 16,
                     kh + ((size_t)(b * S_ + (kt + 1) * 128 + row)) * D_ + h * DK + ch * 8);
            }
            cp_commit();
            cp_wait<1>();
        } else {
            cp_wait<0>();
        }
        __syncthreads();

        const __half* Kh = (const __half*)(smc + (1 + buf) * P1T);

        float acc[2][8][4];
#pragma unroll
        for (int mt = 0; mt < 2; mt++)
#pragma unroll
            for (int nt = 0; nt < 8; nt++)
#pragma unroll
                for (int e = 0; e < 4; e++) acc[mt][nt][e] = 0.f;

#pragma unroll
        for (int kk = 0; kk < 4; kk++) {
#pragma unroll
            for (int nt = 0; nt < 8; nt++) {
                int c = wn * 64 + nt * 8 + grp;
                int c0 = kk * 16 + qid * 2;
                unsigned b0 = *(const unsigned*)&Kh[c * P1S + c0];
                unsigned b1 = *(const unsigned*)&Kh[c * P1S + c0 + 8];
#pragma unroll
                for (int mt = 0; mt < 2; mt++)
                    mma16816(acc[mt][nt], qf[mt][kk], b0, b1);
            }
        }

#pragma unroll
        for (int mt = 0; mt < 2; mt++) {
            int r = q0 + wm * 32 + mt * 16 + grp;
#pragma unroll
            for (int nt = 0; nt < 8; nt++) {
                int c = kt * 128 + wn * 64 + nt * 8 + qid * 2;
                float s0 = acc[mt][nt][0] * 0.125f, s1 = acc[mt][nt][1] * 0.125f;
                float s2 = acc[mt][nt][2] * 0.125f, s3 = acc[mt][nt][3] * 0.125f;
                *(__half2*)&g_sh[((size_t)bh * S_ + r) * S_ + c]     = __floats2half2_rn(s0, s1);
                *(__half2*)&g_sh[((size_t)bh * S_ + r + 8) * S_ + c] = __floats2half2_rn(s2, s3);
                zacc[0][0] = zacc[0][0];  // keep structure
                zacc[mt][0] += __expf(s0) + __expf(s1);
                zacc[mt][1] += __expf(s2) + __expf(s3);
            }
        }
        __syncthreads();
    }

#pragma unroll
    for (int mt = 0; mt < 2; mt++)
#pragma unroll
        for (int hf = 0; hf < 2; hf++) {
            float z = zacc[mt][hf];
            z += __shfl_xor_sync(0xffffffffu, z, 1);
            z += __shfl_xor_sync(0xffffffffu, z, 2);
            if (qid == 0) zbuf[wn * 128 + wm * 32 + mt * 16 + hf * 8 + grp] = z;
        }
    __syncthreads();
    if (tid < 128) sz[tid] = zbuf[tid] + zbuf[128 + tid];
    __syncthreads();

    // ======== phase B ========
    __half* Th = (__half*)smc;
    const __half* Vh = (const __half*)(smc + P2TT);
    float* tsums = (float*)(smc + P2TT + P2VT);

    float iz[8], tsum[8];
#pragma unroll
    for (int i = 0; i < 8; i++) {
        iz[i] = 1.0f / sz[ty * 8 + i];
        tsum[i] = 0.f;
    }

    float acc2[2][4][4];
#pragma unroll
    for (int mt = 0; mt < 2; mt++)
#pragma unroll
        for (int nt = 0; nt < 4; nt++)
#pragma unroll
            for (int e = 0; e < 4; e++) acc2[mt][nt][e] = 0.f;

    for (int kt = 0; kt < 16; kt++) {
        const int k0 = kt * 128;
        {
#pragma unroll
            for (int u = 0; u < 4; u++) {
                int idx = tid * 4 + u;                 // 0..1023
                int row = idx >> 4, ch = idx & 15;
                cp16(sb + P2TT + row * P2ROW + ch * 16,
                     vth + ((size_t)bh * DK + row) * S_ + k0 + ch * 8);
            }
            cp_commit();
        }
#pragma unroll
        for (int i = 0; i < 8; i++) {
            int r = ty * 8 + i;
#pragma unroll
            for (int hf = 0; hf < 2; hf++) {
                int c = hf * 64 + tx * 4;
                struct alignas(8) H4 { __half2 a, b; };
                H4 s4 = *(const H4*)&g_sh[((size_t)bh * S_ + q0 + r) * S_ + k0 + c];
                float2 f01 = __half22float2(s4.a);
                float2 f23 = __half22float2(s4.b);
                float p0 = __expf(f01.x) * iz[i];
                float p1 = __expf(f01.y) * iz[i];
                float p2 = __expf(f23.x) * iz[i];
                float p3 = __expf(f23.y) * iz[i];
                float t0 = fmaf(0.5f * p0, p0, p0);   // expm1(p)
                float t1 = fmaf(0.5f * p1, p1, p1);
                float t2 = fmaf(0.5f * p2, p2, p2);
                float t3 = fmaf(0.5f * p3, p3, p3);
                tsum[i] += (t0 + t1) + (t2 + t3);
                *(__half2*)&Th[r * P2S + c]     = __floats2half2_rn(t0, t1);
                *(__half2*)&Th[r * P2S + c + 2] = __floats2half2_rn(t2, t3);
            }
        }
        cp_wait<0>();
        __syncthreads();

#pragma unroll
        for (int kk = 0; kk < 8; kk++) {
            unsigned af[2][4];
            int c0 = kk * 16 + qid * 2;
#pragma unroll
            for (int mt = 0; mt < 2; mt++) {
                int r = wm * 32 + mt * 16 + grp;
                af[mt][0] = *(const unsigned*)&Th[r * P2S + c0];
                af[mt][1] = *(const unsigned*)&Th[(r + 8) * P2S + c0];
                af[mt][2] = *(const unsigned*)&Th[r * P2S + c0 + 8];
                af[mt][3] = *(const unsigned*)&Th[(r + 8) * P2S + c0 + 8];
            }
#pragma unroll
            for (int nt = 0; nt < 4; nt++) {
                int c = wn * 32 + nt * 8 + grp;
                unsigned b0 = *(const unsigned*)&Vh[c * P2S + c0];
                unsigned b1 = *(const unsigned*)&Vh[c * P2S + c0 + 8];
#pragma unroll
                for (int mt = 0; mt < 2; mt++)
                    mma16816(acc2[mt][nt], af[mt], b0, b1);
            }
        }
        __syncthreads();
    }

#pragma unroll
    for (int i = 0; i < 8; i++) {
        float s = tsum[i];
        s += __shfl_xor_sync(0xffffffffu, s, 1);
        s += __shfl_xor_sync(0xffffffffu, s, 2);
        s += __shfl_xor_sync(0xffffffffu, s, 4);
        s += __shfl_xor_sync(0xffffffffu, s, 8);
        if (tx == 0) tsums[ty * 8 + i] = s;
    }
    __syncthreads();

    // epilogue: out = (sumv + acc) / (2048 + sum p') -> fp16
#pragma unroll
    for (int mt = 0; mt < 2; mt++) {
        int rl0 = wm * 32 + mt * 16 + grp;
        float r0 = 1.0f / (2048.0f + tsums[rl0]);
        float r1 = 1.0f / (2048.0f + tsums[rl0 + 8]);
#pragma unroll
        for (int nt = 0; nt < 4; nt++) {
            int dcol = wn * 32 + nt * 8 + qid * 2;
            float sv0 = sumv[bh * DK + dcol];
            float sv1 = sumv[bh * DK + dcol + 1];
            int c = h * DK + dcol;
            size_t o0 = ((size_t)(b * S_ + q0 + rl0)) * D_ + c;
            size_t o1 = ((size_t)(b * S_ + q0 + rl0 + 8)) * D_ + c;
            *(__half2*)&aout[o0] = __floats2half2_rn((sv0 + acc2[mt][nt][0]) * r0,
                                                     (sv1 + acc2[mt][nt][1]) * r0);
            *(__half2*)&aout[o1] = __floats2half2_rn((sv0 + acc2[mt][nt][2]) * r1,
                                                     (sv1 + acc2[mt][nt][3]) * r1);
        }
    }
}

// ---------------- launch ----------------
extern "C" void kernel_launch(void* const* d_in, const int* in_sizes, int n_in,
                              void* d_out, int out_size) {
    const float* x  = (const float*)d_in[0];
    const float* fc = (const float*)d_in[1];
    const float* fs = (const float*)d_in[2];
    const float* W[4] = {(const float*)d_in[3], (const float*)d_in[4],
                         (const float*)d_in[5], (const float*)d_in[6]};
    float* out = (float*)d_out;

    float *v, *sumvp;
    __half *xh, *ah, *wt, *qh, *kh, *vth;
    cudaGetSymbolAddress((void**)&v, g_v);
    cudaGetSymbolAddress((void**)&sumvp, g_sumv);
    cudaGetSymbolAddress((void**)&xh, g_xh);
    cudaGetSymbolAddress((void**)&ah, g_ah);
    cudaGetSymbolAddress((void**)&wt, g_wt);
    cudaGetSymbolAddress((void**)&qh, g_qh);
    cudaGetSymbolAddress((void**)&kh, g_kh);
    cudaGetSymbolAddress((void**)&vth, g_vth);

    cudaFuncSetAttribute(gemm_f16, cudaFuncAttributeMaxDynamicSharedMemorySize, G1SMEM);
    cudaFuncSetAttribute(gemm_rope, cudaFuncAttributeMaxDynamicSharedMemorySize, G1SMEM);
    cudaFuncSetAttribute(attn_fused, cudaFuncAttributeMaxDynamicSharedMemorySize, FASMEM);

    convX<<<(MS_ * D_) / 256, 256>>>(x, xh);
    for (int i = 0; i < 4; i++)
        convWT<<<dim3(32, 32), 256>>>(W[i], wt + (size_t)i * D_ * D_);

    dim3 ggrid(8, 32);
    gemm_rope<<<ggrid, 256, G1SMEM>>>(xh, wt + 0 * (size_t)D_ * D_, fc, fs, qh);
    gemm_rope<<<ggrid, 256, G1SMEM>>>(xh, wt + 1 * (size_t)D_ * D_, fc, fs, kh);
    gemm_f16<<<ggrid, 256, G1SMEM>>>(xh, wt + 2 * (size_t)D_ * D_, v);

    vtrans<<<dim3(S_ / 32, DK / 32, BH_), 256>>>(v, vth);
    sumv_kernel<<<BH_, 256>>>(v, sumvp);

    attn_fused<<<dim3(S_ / 128, BH_), 256, FASMEM>>>(qh, kh, vth, sumvp, ah);

    gemm_f16<<<ggrid, 256, G1SMEM>>>(ah, wt + 3 * (size_t)D_ * D_, out);
}